// round 4
// baseline (speedup 1.0000x reference)
#include <cuda_runtime.h>
#include <cuda_bf16.h>
#include <cstdint>

// ---------------------------------------------------------------------------
// Problem constants
// ---------------------------------------------------------------------------
constexpr int B = 64;
constexpr int I = 512;
constexpr int T = 512;
constexpr int H = 1024;
constexpr float DECAY = 0.8f;

// ---------------------------------------------------------------------------
// Device scratch
// ---------------------------------------------------------------------------
__device__ __nv_bfloat16 g_Ah[(size_t)B * T * I];   // x^T hi  (b, t, i) K-major
__device__ __nv_bfloat16 g_Al[(size_t)B * T * I];   // x^T lo
__device__ __nv_bfloat16 g_Wh[(size_t)H * I];       // W^T hi  (h, i) K-major
__device__ __nv_bfloat16 g_Wl[(size_t)H * I];       // W^T lo
__device__ float         g_proj[(size_t)T * B * H]; // proj (t, b, h)

// ---------------------------------------------------------------------------
// PTX helpers (all plain compute_103 / sm_80-era features)
// ---------------------------------------------------------------------------
__device__ __forceinline__ uint32_t s2u(const void* p) {
    uint32_t a;
    asm("{ .reg .u64 t; cvta.to.shared.u64 t, %1; cvt.u32.u64 %0, t; }"
        : "=r"(a) : "l"(p));
    return a;
}
__device__ __forceinline__ void cp16(uint32_t dst, const void* src) {
    asm volatile("cp.async.cg.shared.global [%0], [%1], 16;" :: "r"(dst), "l"(src));
}
__device__ __forceinline__ void cp_commit() {
    asm volatile("cp.async.commit_group;" ::: "memory");
}
template <int N>
__device__ __forceinline__ void cp_wait() {
    asm volatile("cp.async.wait_group %0;" :: "n"(N) : "memory");
}
__device__ __forceinline__ void ldm_x4(uint32_t& r0, uint32_t& r1, uint32_t& r2,
                                       uint32_t& r3, uint32_t addr) {
    asm volatile("ldmatrix.sync.aligned.m8n8.x4.shared.b16 {%0,%1,%2,%3}, [%4];"
                 : "=r"(r0), "=r"(r1), "=r"(r2), "=r"(r3) : "r"(addr));
}
__device__ __forceinline__ void mma16816(float* d, const uint32_t* a,
                                         uint32_t b0, uint32_t b1) {
    asm volatile(
        "mma.sync.aligned.m16n8k16.row.col.f32.bf16.bf16.f32 "
        "{%0,%1,%2,%3}, {%4,%5,%6,%7}, {%8,%9}, {%0,%1,%2,%3};"
        : "+f"(d[0]), "+f"(d[1]), "+f"(d[2]), "+f"(d[3])
        : "r"(a[0]), "r"(a[1]), "r"(a[2]), "r"(a[3]), "r"(b0), "r"(b1));
}

// ---------------------------------------------------------------------------
// Kernel 1: transpose + hi/lo split of x: (B,I,T) fp32 -> (B,T,I) bf16 x2
// ---------------------------------------------------------------------------
__global__ __launch_bounds__(256)
void conv_x(const float* __restrict__ x) {
    __shared__ float tile[32][33];
    const int b  = blockIdx.z;
    const int t0 = blockIdx.x * 32;
    const int i0 = blockIdx.y * 32;
    const int tx = threadIdx.x;
    const int ty = threadIdx.y;

    const float* src = x + ((size_t)b * I + i0) * T + t0;
#pragma unroll
    for (int k = 0; k < 4; ++k)
        tile[ty + k * 8][tx] = src[(size_t)(ty + k * 8) * T + tx];
    __syncthreads();

    __nv_bfloat16* dh = g_Ah + ((size_t)b * T + t0) * I + i0;
    __nv_bfloat16* dl = g_Al + ((size_t)b * T + t0) * I + i0;
#pragma unroll
    for (int k = 0; k < 4; ++k) {
        const int r = ty + k * 8;
        const float v = tile[tx][r];
        const __nv_bfloat16 hi = __float2bfloat16(v);
        const __nv_bfloat16 lo = __float2bfloat16(v - __bfloat162float(hi));
        dh[(size_t)r * I + tx] = hi;
        dl[(size_t)r * I + tx] = lo;
    }
}

// ---------------------------------------------------------------------------
// Kernel 2: transpose + hi/lo split of W: (I,H) fp32 -> (H,I) bf16 x2
// ---------------------------------------------------------------------------
__global__ __launch_bounds__(256)
void conv_w(const float* __restrict__ W) {
    __shared__ float tile[32][33];
    const int h0 = blockIdx.x * 32;
    const int i0 = blockIdx.y * 32;
    const int tx = threadIdx.x;
    const int ty = threadIdx.y;

    const float* src = W + ((size_t)i0) * H + h0;
#pragma unroll
    for (int k = 0; k < 4; ++k)
        tile[ty + k * 8][tx] = src[(size_t)(ty + k * 8) * H + tx];
    __syncthreads();

    __nv_bfloat16* dh = g_Wh + ((size_t)h0) * I + i0;
    __nv_bfloat16* dl = g_Wl + ((size_t)h0) * I + i0;
#pragma unroll
    for (int k = 0; k < 4; ++k) {
        const int r = ty + k * 8;
        const float v = tile[tx][r];
        const __nv_bfloat16 hi = __float2bfloat16(v);
        const __nv_bfloat16 lo = __float2bfloat16(v - __bfloat162float(hi));
        dh[(size_t)r * I + tx] = hi;
        dl[(size_t)r * I + tx] = lo;
    }
}

// ---------------------------------------------------------------------------
// Kernel 3: bf16-split GEMM via mma.sync (HMMA).
// D[128 t, 128 h] fp32 accumulators in registers; effective K = 1536:
//   phase 0: A_hi*W_hi, phase 1: A_hi*W_lo, phase 2: A_lo*W_hi
// 4-stage cp.async pipeline, KC=32 per stage (2 k16 steps).
// ---------------------------------------------------------------------------
constexpr int BM = 128, BN = 128, KC = 32;
constexpr int STAGES = 4;
constexpr int NSTG = 3 * (I / KC);              // 48
constexpr int ROWE = KC + 8;                    // 40 elems (pad 8 -> conflict-free)
constexpr int ROWB = ROWE * 2;                  // 80 bytes
constexpr int TILE_BYTES  = BM * ROWB;          // 10240
constexpr int STAGE_BYTES = 2 * TILE_BYTES;     // 20480 (A then B)
constexpr int SMEM_DYN = STAGES * STAGE_BYTES;  // 81920

__global__ __launch_bounds__(256, 2)
void gemm_mma() {
    extern __shared__ __align__(128) char smem[];
    const uint32_t sb = s2u(smem);
    const int tid  = threadIdx.x;
    const int warp = tid >> 5;
    const int lane = tid & 31;
    const int b  = blockIdx.z;
    const int t0 = blockIdx.y * BM;
    const int h0 = blockIdx.x * BN;

    const int wm = warp & 1;        // 2 warp-rows  (m extent 64)
    const int wn = warp >> 1;       // 4 warp-cols  (n extent 32)

    // Per-thread cp.async mapping: 2 A-chunks + 2 B-chunks of 16B per stage.
    const int r0 = tid >> 1;                    // row for j=0/1 (same row)
    const int c0 = (tid * 2) & 3;               // 16B-column for j=0
    const int c1 = c0 + 1;

    auto load_stage = [&](int s) {
        const int ph = s >> 4;                  // 16 stages per product phase
        const int kc = s & 15;
        const size_t i0 = (size_t)kc * KC;
        const __nv_bfloat16* Ap =
            (ph == 2 ? g_Al : g_Ah) + ((size_t)(b * T + t0)) * I + i0;
        const __nv_bfloat16* Bp =
            (ph == 1 ? g_Wl : g_Wh) + ((size_t)h0) * I + i0;
        const uint32_t sA = sb + (s % STAGES) * STAGE_BYTES;
        const uint32_t sB = sA + TILE_BYTES;
        cp16(sA + r0 * ROWB + c0 * 16, Ap + (size_t)r0 * I + c0 * 8);
        cp16(sA + r0 * ROWB + c1 * 16, Ap + (size_t)r0 * I + c1 * 8);
        cp16(sB + r0 * ROWB + c0 * 16, Bp + (size_t)r0 * I + c0 * 8);
        cp16(sB + r0 * ROWB + c1 * 16, Bp + (size_t)r0 * I + c1 * 8);
    };

    // Prologue: fill 3 stages
    load_stage(0); cp_commit();
    load_stage(1); cp_commit();
    load_stage(2); cp_commit();

    float acc[4][4][4];
#pragma unroll
    for (int mt = 0; mt < 4; ++mt)
#pragma unroll
        for (int nj = 0; nj < 4; ++nj)
#pragma unroll
            for (int r = 0; r < 4; ++r) acc[mt][nj][r] = 0.0f;

    // ldmatrix lane->row offsets (within tile), fixed per thread:
    const int a_row = (lane & 15);              // tiles 0/1: m rows, 2/3: +k8
    const int a_kh  = (lane >> 4) * 8;
    const int b_row = (lane & 7) + ((lane >> 4) << 3);
    const int b_kh  = ((lane >> 3) & 1) * 8;

    for (int s = 0; s < NSTG; ++s) {
        cp_wait<STAGES - 2>();                  // stage s resident
        __syncthreads();
        if (s + STAGES - 1 < NSTG) load_stage(s + STAGES - 1);
        cp_commit();

        const uint32_t sA = sb + (s % STAGES) * STAGE_BYTES;
        const uint32_t sB = sA + TILE_BYTES;

#pragma unroll
        for (int kk = 0; kk < KC; kk += 16) {
            uint32_t a[4][4], bb[2][4];
#pragma unroll
            for (int mt = 0; mt < 4; ++mt) {
                const int m = wm * 64 + mt * 16 + a_row;
                ldm_x4(a[mt][0], a[mt][1], a[mt][2], a[mt][3],
                       sA + m * ROWB + (kk + a_kh) * 2);
            }
#pragma unroll
            for (int nt = 0; nt < 2; ++nt) {
                const int n = wn * 32 + nt * 16 + b_row;
                ldm_x4(bb[nt][0], bb[nt][1], bb[nt][2], bb[nt][3],
                       sB + n * ROWB + (kk + b_kh) * 2);
            }
#pragma unroll
            for (int mt = 0; mt < 4; ++mt)
#pragma unroll
                for (int nj = 0; nj < 4; ++nj) {
                    const int nt = nj >> 1;
                    const int hh = (nj & 1) * 2;
                    mma16816(acc[mt][nj], a[mt], bb[nt][hh], bb[nt][hh + 1]);
                }
        }
        __syncthreads();   // all warps done with stage s before it is refilled
    }

    // Epilogue: write acc -> g_proj (t, b, h)
#pragma unroll
    for (int mt = 0; mt < 4; ++mt) {
        const int tg = t0 + wm * 64 + mt * 16 + (lane >> 2);
#pragma unroll
        for (int nj = 0; nj < 4; ++nj) {
            const int h = h0 + wn * 32 + nj * 8 + (lane & 3) * 2;
            float* o0 = g_proj + ((size_t)tg * B + b) * H + h;
            float* o1 = g_proj + ((size_t)(tg + 8) * B + b) * H + h;
            *(float2*)o0 = make_float2(acc[mt][nj][0], acc[mt][nj][1]);
            *(float2*)o1 = make_float2(acc[mt][nj][2], acc[mt][nj][3]);
        }
    }
}

// ---------------------------------------------------------------------------
// Kernel 4: sequential recurrence (unchanged)
// ---------------------------------------------------------------------------
__global__ __launch_bounds__(256)
void scan_kernel(const float* __restrict__ bias, float* __restrict__ out) {
    const int gid = blockIdx.x * blockDim.x + threadIdx.x;
    const int b = gid >> 10;
    const int h = gid & (H - 1);

    const float bv = __ldg(bias + h);
    const float* p = g_proj + (size_t)b * H + h;
    constexpr int STRIDE = B * H;
    constexpr int CH = 16;

    float hc = 0.0f, y = 0.0f;
    float buf[CH];
#pragma unroll
    for (int j = 0; j < CH; ++j) buf[j] = p[(size_t)j * STRIDE];

    for (int tt = 0; tt < T; tt += CH) {
        float nbuf[CH];
        if (tt + CH < T) {
            const float* pn = p + (size_t)(tt + CH) * STRIDE;
#pragma unroll
            for (int j = 0; j < CH; ++j) nbuf[j] = pn[(size_t)j * STRIDE];
        } else {
#pragma unroll
            for (int j = 0; j < CH; ++j) nbuf[j] = 0.0f;
        }
#pragma unroll
        for (int j = 0; j < CH; ++j) {
            hc = fmaxf(buf[j] + DECAY * hc * (1.0f - y), 0.0f);
            const float z = hc + bv;
            y = (z > 1.0f) ? z : 0.0f;
        }
#pragma unroll
        for (int j = 0; j < CH; ++j) buf[j] = nbuf[j];
    }
    out[gid] = y;
}

// ---------------------------------------------------------------------------
extern "C" void kernel_launch(void* const* d_in, const int* in_sizes, int n_in,
                              void* d_out, int out_size) {
    const float* x    = (const float*)d_in[0];  // (B, I, T)
    const float* W    = (const float*)d_in[1];  // (I, H)
    const float* bias = (const float*)d_in[2];  // (1, H)
    float* out        = (float*)d_out;          // (B, H)

    cudaFuncSetAttribute(gemm_mma, cudaFuncAttributeMaxDynamicSharedMemorySize,
                         SMEM_DYN);

    conv_x<<<dim3(T / 32, I / 32, B), dim3(32, 8)>>>(x);
    conv_w<<<dim3(H / 32, I / 32), dim3(32, 8)>>>(W);
    gemm_mma<<<dim3(H / BN, T / BM, B), 256, SMEM_DYN>>>();
    scan_kernel<<<(B * H) / 256, 256>>>(bias, out);
}

// round 6
// speedup vs baseline: 1.1922x; 1.1922x over previous
#include <cuda_runtime.h>
#include <cuda_fp16.h>
#include <cstdint>

// ---------------------------------------------------------------------------
// Problem constants
// ---------------------------------------------------------------------------
constexpr int B = 64;
constexpr int I = 512;
constexpr int T = 512;
constexpr int H = 1024;
constexpr float DECAY = 0.8f;

// ---------------------------------------------------------------------------
// Device scratch
// ---------------------------------------------------------------------------
__device__ __half g_Axh[(size_t)B * T * I];         // fp16 hi of x^T (b,t,i)
__device__ __half g_Axl[(size_t)B * T * I];         // fp16 lo of x^T
__device__ __half g_Wh[(size_t)H * I];              // fp16 hi of W^T (h,i)
__device__ __half g_Wl[(size_t)H * I];              // fp16 lo of W^T
__device__ float  g_proj[(size_t)T * B * H];        // proj (t, b, h)

// ---------------------------------------------------------------------------
// PTX helpers (plain compute_103 features only)
// ---------------------------------------------------------------------------
__device__ __forceinline__ uint32_t s2u(const void* p) {
    uint32_t a;
    asm("{ .reg .u64 t; cvta.to.shared.u64 t, %1; cvt.u32.u64 %0, t; }"
        : "=r"(a) : "l"(p));
    return a;
}
__device__ __forceinline__ void cp16(uint32_t dst, const void* src) {
    asm volatile("cp.async.cg.shared.global [%0], [%1], 16;" :: "r"(dst), "l"(src));
}
__device__ __forceinline__ void cp_commit() {
    asm volatile("cp.async.commit_group;" ::: "memory");
}
template <int N>
__device__ __forceinline__ void cp_wait() {
    asm volatile("cp.async.wait_group %0;" :: "n"(N) : "memory");
}
__device__ __forceinline__ void ldm_x4(uint32_t& r0, uint32_t& r1, uint32_t& r2,
                                       uint32_t& r3, uint32_t addr) {
    asm volatile("ldmatrix.sync.aligned.m8n8.x4.shared.b16 {%0,%1,%2,%3}, [%4];"
                 : "=r"(r0), "=r"(r1), "=r"(r2), "=r"(r3) : "r"(addr));
}
__device__ __forceinline__ void mma16816(float* d, const uint32_t* a,
                                         uint32_t b0, uint32_t b1) {
    asm volatile(
        "mma.sync.aligned.m16n8k16.row.col.f32.f16.f16.f32 "
        "{%0,%1,%2,%3}, {%4,%5,%6,%7}, {%8,%9}, {%0,%1,%2,%3};"
        : "+f"(d[0]), "+f"(d[1]), "+f"(d[2]), "+f"(d[3])
        : "r"(a[0]), "r"(a[1]), "r"(a[2]), "r"(a[3]), "r"(b0), "r"(b1));
}

// ---------------------------------------------------------------------------
// Kernel 1: transpose x (B,I,T) fp32 -> (B,T,I) fp16 hi/lo
// ---------------------------------------------------------------------------
__global__ __launch_bounds__(256)
void conv_x(const float* __restrict__ x) {
    __shared__ float tile[32][33];
    const int b  = blockIdx.z;
    const int t0 = blockIdx.x * 32;
    const int i0 = blockIdx.y * 32;
    const int tx = threadIdx.x;
    const int ty = threadIdx.y;

    const float* src = x + ((size_t)b * I + i0) * T + t0;
#pragma unroll
    for (int k = 0; k < 4; ++k)
        tile[ty + k * 8][tx] = src[(size_t)(ty + k * 8) * T + tx];
    __syncthreads();

    __half* dh = g_Axh + ((size_t)b * T + t0) * I + i0;
    __half* dl = g_Axl + ((size_t)b * T + t0) * I + i0;
#pragma unroll
    for (int k = 0; k < 4; ++k) {
        const int r = ty + k * 8;
        const float v = tile[tx][r];
        const __half hi = __float2half(v);
        const __half lo = __float2half(v - __half2float(hi));
        dh[(size_t)r * I + tx] = hi;
        dl[(size_t)r * I + tx] = lo;
    }
}

// ---------------------------------------------------------------------------
// Kernel 2: transpose W (I,H) fp32 -> (H,I) fp16 hi/lo
// ---------------------------------------------------------------------------
__global__ __launch_bounds__(256)
void conv_w(const float* __restrict__ W) {
    __shared__ float tile[32][33];
    const int h0 = blockIdx.x * 32;
    const int i0 = blockIdx.y * 32;
    const int tx = threadIdx.x;
    const int ty = threadIdx.y;

    const float* src = W + ((size_t)i0) * H + h0;
#pragma unroll
    for (int k = 0; k < 4; ++k)
        tile[ty + k * 8][tx] = src[(size_t)(ty + k * 8) * H + tx];
    __syncthreads();

    __half* dh = g_Wh + ((size_t)h0) * I + i0;
    __half* dl = g_Wl + ((size_t)h0) * I + i0;
#pragma unroll
    for (int k = 0; k < 4; ++k) {
        const int r = ty + k * 8;
        const float v = tile[tx][r];
        const __half hi = __float2half(v);
        const __half lo = __float2half(v - __half2float(hi));
        dh[(size_t)r * I + tx] = hi;
        dl[(size_t)r * I + tx] = lo;
    }
}

// ---------------------------------------------------------------------------
// Kernel 3: hybrid GEMM. Even CTAs: fp32 SGEMM (h in [0,512), FMA pipe).
//           Odd CTAs: fp16 3-product MMA (h in [512,1024), tensor pipe).
// Both: tile D[128 t, 128 h] per CTA. 1024 CTAs per role.
// ---------------------------------------------------------------------------
constexpr int BM = 128, BN = 128;

// mma-path config
constexpr int KC = 32;
constexpr int STAGES = 4;
constexpr int NSTG = 3 * (I / KC);              // 48
constexpr int ROWE = KC + 8;                    // 40 (pad -> conflict-free ldmatrix)
constexpr int ROWB = ROWE * 2;                  // 80 bytes
constexpr int TILE_BYTES  = BM * ROWB;          // 10240
constexpr int STAGE_BYTES = 2 * TILE_BYTES;     // 20480
constexpr int SMEM_DYN = STAGES * STAGE_BYTES;  // 81920 (fp32 path uses 32KB of it)

// fp32-path config
constexpr int FK = 16;                          // k-tile
constexpr int FTM = 8, FTN = 8;

__global__ __launch_bounds__(256, 2)
void gemm_hybrid(const float* __restrict__ x, const float* __restrict__ W) {
    extern __shared__ __align__(128) char smem[];
    const int tid  = threadIdx.x;
    const int role = blockIdx.x & 1;
    const int q    = blockIdx.x >> 1;           // 0..1023
    const int hb   = q & 3;
    const int tb   = (q >> 2) & 3;
    const int b    = q >> 4;
    const int t0   = tb * BM;

    if (role == 0) {
        // ---------------- fp32 SGEMM, h0 in [0,512) ----------------
        const int h0 = hb * BN;
        float* As = (float*)smem;                       // [2][FK][BM]
        float* Bs = As + 2 * FK * BM;                   // [2][FK][BN]

        const float* Ab = x + (size_t)b * I * T + t0;   // (i,t): Ab[i*T+t]
        const float* Bb = W + h0;                       // (i,n): Bb[i*H+n]

        const int idx0 = tid, idx1 = tid + 256;
        const int ka0 = idx0 >> 5, ma0 = (idx0 & 31) << 2;
        const int ka1 = idx1 >> 5, ma1 = (idx1 & 31) << 2;

        float4 aR0 = *(const float4*)(Ab + (size_t)ka0 * T + ma0);
        float4 aR1 = *(const float4*)(Ab + (size_t)ka1 * T + ma1);
        float4 bR0 = *(const float4*)(Bb + (size_t)ka0 * H + ma0);
        float4 bR1 = *(const float4*)(Bb + (size_t)ka1 * H + ma1);
        *(float4*)&As[(0 * FK + ka0) * BM + ma0] = aR0;
        *(float4*)&As[(0 * FK + ka1) * BM + ma1] = aR1;
        *(float4*)&Bs[(0 * FK + ka0) * BN + ma0] = bR0;
        *(float4*)&Bs[(0 * FK + ka1) * BN + ma1] = bR1;
        __syncthreads();

        const int tx  = tid & 15;
        const int ty  = tid >> 4;
        const int tm0 = ty * FTM;
        const int tn0 = tx * FTN;

        float acc[FTM][FTN];
#pragma unroll
        for (int i = 0; i < FTM; ++i)
#pragma unroll
            for (int j = 0; j < FTN; ++j) acc[i][j] = 0.0f;

        constexpr int KT = I / FK;              // 32
        int p = 0;
        for (int kt = 0; kt < KT; ++kt) {
            if (kt + 1 < KT) {
                const float* An = Ab + (size_t)(kt + 1) * FK * T;
                const float* Bn = Bb + (size_t)(kt + 1) * FK * H;
                aR0 = *(const float4*)(An + (size_t)ka0 * T + ma0);
                aR1 = *(const float4*)(An + (size_t)ka1 * T + ma1);
                bR0 = *(const float4*)(Bn + (size_t)ka0 * H + ma0);
                bR1 = *(const float4*)(Bn + (size_t)ka1 * H + ma1);
            }
#pragma unroll
            for (int kk = 0; kk < FK; ++kk) {
                float a[FTM], bb[FTN];
                *(float4*)&a[0]  = *(const float4*)&As[(p * FK + kk) * BM + tm0];
                *(float4*)&a[4]  = *(const float4*)&As[(p * FK + kk) * BM + tm0 + 4];
                *(float4*)&bb[0] = *(const float4*)&Bs[(p * FK + kk) * BN + tn0];
                *(float4*)&bb[4] = *(const float4*)&Bs[(p * FK + kk) * BN + tn0 + 4];
#pragma unroll
                for (int i = 0; i < FTM; ++i)
#pragma unroll
                    for (int j = 0; j < FTN; ++j)
                        acc[i][j] += a[i] * bb[j];
            }
            if (kt + 1 < KT) {
                const int pq = p ^ 1;
                *(float4*)&As[(pq * FK + ka0) * BM + ma0] = aR0;
                *(float4*)&As[(pq * FK + ka1) * BM + ma1] = aR1;
                *(float4*)&Bs[(pq * FK + ka0) * BN + ma0] = bR0;
                *(float4*)&Bs[(pq * FK + ka1) * BN + ma1] = bR1;
                __syncthreads();
                p = pq;
            }
        }

#pragma unroll
        for (int i = 0; i < FTM; ++i) {
            const int t = t0 + tm0 + i;
            float* out = g_proj + ((size_t)t * B + b) * H + h0 + tn0;
            *(float4*)(out)     = make_float4(acc[i][0], acc[i][1], acc[i][2], acc[i][3]);
            *(float4*)(out + 4) = make_float4(acc[i][4], acc[i][5], acc[i][6], acc[i][7]);
        }
    } else {
        // ---------------- fp16 3-product MMA, h0 in [512,1024) ----------------
        const int h0 = 512 + hb * BN;
        const uint32_t sb = s2u(smem);
        const int warp = tid >> 5;
        const int lane = tid & 31;
        const int wm = warp & 1;
        const int wn = warp >> 1;

        const int r0 = tid >> 1;
        const int c0 = (tid * 2) & 3;
        const int c1 = c0 + 1;

        const __half* Ah = g_Axh + ((size_t)(b * T + t0)) * I;
        const __half* Al = g_Axl + ((size_t)(b * T + t0)) * I;
        const __half* Bh = g_Wh + ((size_t)h0) * I;
        const __half* Bl = g_Wl + ((size_t)h0) * I;

        auto load_stage = [&](int s) {
            const int ph = s >> 4;
            const int kc = s & 15;
            const size_t i0 = (size_t)kc * KC;
            const __half* Ap = (ph == 2 ? Al : Ah) + i0;   // hi,hi,lo
            const __half* Bp = (ph == 1 ? Bl : Bh) + i0;   // hi,lo,hi
            const uint32_t sA = sb + (s % STAGES) * STAGE_BYTES;
            const uint32_t sB = sA + TILE_BYTES;
            cp16(sA + r0 * ROWB + c0 * 16, Ap + (size_t)r0 * I + c0 * 8);
            cp16(sA + r0 * ROWB + c1 * 16, Ap + (size_t)r0 * I + c1 * 8);
            cp16(sB + r0 * ROWB + c0 * 16, Bp + (size_t)r0 * I + c0 * 8);
            cp16(sB + r0 * ROWB + c1 * 16, Bp + (size_t)r0 * I + c1 * 8);
        };

        load_stage(0); cp_commit();
        load_stage(1); cp_commit();
        load_stage(2); cp_commit();

        float acc[4][4][4];
#pragma unroll
        for (int mt = 0; mt < 4; ++mt)
#pragma unroll
            for (int nj = 0; nj < 4; ++nj)
#pragma unroll
                for (int r = 0; r < 4; ++r) acc[mt][nj][r] = 0.0f;

        const int a_row = (lane & 15);
        const int a_kh  = (lane >> 4) * 8;
        const int b_row = (lane & 7) + ((lane >> 4) << 3);
        const int b_kh  = ((lane >> 3) & 1) * 8;

        for (int s = 0; s < NSTG; ++s) {
            cp_wait<STAGES - 2>();
            __syncthreads();
            if (s + STAGES - 1 < NSTG) load_stage(s + STAGES - 1);
            cp_commit();

            const uint32_t sA = sb + (s % STAGES) * STAGE_BYTES;
            const uint32_t sB = sA + TILE_BYTES;

#pragma unroll
            for (int kk = 0; kk < KC; kk += 16) {
                uint32_t a[4][4], bb[2][4];
#pragma unroll
                for (int mt = 0; mt < 4; ++mt) {
                    const int m = wm * 64 + mt * 16 + a_row;
                    ldm_x4(a[mt][0], a[mt][1], a[mt][2], a[mt][3],
                           sA + m * ROWB + (kk + a_kh) * 2);
                }
#pragma unroll
                for (int nt = 0; nt < 2; ++nt) {
                    const int n = wn * 32 + nt * 16 + b_row;
                    ldm_x4(bb[nt][0], bb[nt][1], bb[nt][2], bb[nt][3],
                           sB + n * ROWB + (kk + b_kh) * 2);
                }
#pragma unroll
                for (int mt = 0; mt < 4; ++mt)
#pragma unroll
                    for (int nj = 0; nj < 4; ++nj) {
                        const int nt = nj >> 1;
                        const int hh = (nj & 1) * 2;
                        mma16816(acc[mt][nj], a[mt], bb[nt][hh], bb[nt][hh + 1]);
                    }
            }
            __syncthreads();
        }

#pragma unroll
        for (int mt = 0; mt < 4; ++mt) {
            const int tg = t0 + wm * 64 + mt * 16 + (lane >> 2);
#pragma unroll
            for (int nj = 0; nj < 4; ++nj) {
                const int h = h0 + wn * 32 + nj * 8 + (lane & 3) * 2;
                float* o0 = g_proj + ((size_t)tg * B + b) * H + h;
                float* o1 = g_proj + ((size_t)(tg + 8) * B + b) * H + h;
                *(float2*)o0 = make_float2(acc[mt][nj][0], acc[mt][nj][1]);
                *(float2*)o1 = make_float2(acc[mt][nj][2], acc[mt][nj][3]);
            }
        }
    }
}

// ---------------------------------------------------------------------------
// Kernel 4: sequential recurrence
// ---------------------------------------------------------------------------
__global__ __launch_bounds__(256)
void scan_kernel(const float* __restrict__ bias, float* __restrict__ out) {
    const int gid = blockIdx.x * blockDim.x + threadIdx.x;
    const int b = gid >> 10;
    const int h = gid & (H - 1);

    const float bv = __ldg(bias + h);
    const float* p = g_proj + (size_t)b * H + h;
    constexpr int STRIDE = B * H;
    constexpr int CH = 16;

    float hc = 0.0f, y = 0.0f;
    float buf[CH];
#pragma unroll
    for (int j = 0; j < CH; ++j) buf[j] = p[(size_t)j * STRIDE];

    for (int tt = 0; tt < T; tt += CH) {
        float nbuf[CH];
        if (tt + CH < T) {
            const float* pn = p + (size_t)(tt + CH) * STRIDE;
#pragma unroll
            for (int j = 0; j < CH; ++j) nbuf[j] = pn[(size_t)j * STRIDE];
        } else {
#pragma unroll
            for (int j = 0; j < CH; ++j) nbuf[j] = 0.0f;
        }
#pragma unroll
        for (int j = 0; j < CH; ++j) {
            hc = fmaxf(buf[j] + DECAY * hc * (1.0f - y), 0.0f);
            const float z = hc + bv;
            y = (z > 1.0f) ? z : 0.0f;
        }
#pragma unroll
        for (int j = 0; j < CH; ++j) buf[j] = nbuf[j];
    }
    out[gid] = y;
}

// ---------------------------------------------------------------------------
extern "C" void kernel_launch(void* const* d_in, const int* in_sizes, int n_in,
                              void* d_out, int out_size) {
    const float* x    = (const float*)d_in[0];  // (B, I, T)
    const float* W    = (const float*)d_in[1];  // (I, H)
    const float* bias = (const float*)d_in[2];  // (1, H)
    float* out        = (float*)d_out;          // (B, H)

    cudaFuncSetAttribute(gemm_hybrid, cudaFuncAttributeMaxDynamicSharedMemorySize,
                         SMEM_DYN);

    conv_x<<<dim3(T / 32, I / 32, B), dim3(32, 8)>>>(x);
    conv_w<<<dim3(H / 32, I / 32), dim3(32, 8)>>>(W);
    gemm_hybrid<<<2048, 256, SMEM_DYN>>>(x, W);
    scan_kernel<<<(B * H) / 256, 256>>>(bias, out);
}

// round 7
// speedup vs baseline: 1.2286x; 1.0305x over previous
#include <cuda_runtime.h>
#include <cuda_fp16.h>
#include <cstdint>

// ---------------------------------------------------------------------------
// Problem constants
// ---------------------------------------------------------------------------
constexpr int B = 64;
constexpr int I = 512;
constexpr int T = 512;
constexpr int H = 1024;
constexpr float DECAY = 0.8f;

// ---------------------------------------------------------------------------
// Device scratch
// ---------------------------------------------------------------------------
__device__ __half g_Axh[(size_t)B * T * I];         // fp16 hi of x^T (b,t,i)
__device__ __half g_Axl[(size_t)B * T * I];         // fp16 lo of x^T
__device__ __half g_Wh[(size_t)H * I];              // fp16 hi of W^T (h,i)
__device__ __half g_Wl[(size_t)H * I];              // fp16 lo of W^T
__device__ float  g_proj[(size_t)T * B * H];        // proj (t, b, h)

// ---------------------------------------------------------------------------
// PTX helpers (plain compute_103 features only)
// ---------------------------------------------------------------------------
__device__ __forceinline__ uint32_t s2u(const void* p) {
    uint32_t a;
    asm("{ .reg .u64 t; cvta.to.shared.u64 t, %1; cvt.u32.u64 %0, t; }"
        : "=r"(a) : "l"(p));
    return a;
}
__device__ __forceinline__ void cp16(uint32_t dst, const void* src) {
    asm volatile("cp.async.cg.shared.global [%0], [%1], 16;" :: "r"(dst), "l"(src));
}
__device__ __forceinline__ void cp_commit() {
    asm volatile("cp.async.commit_group;" ::: "memory");
}
template <int N>
__device__ __forceinline__ void cp_wait() {
    asm volatile("cp.async.wait_group %0;" :: "n"(N) : "memory");
}
__device__ __forceinline__ void ldm_x4(uint32_t& r0, uint32_t& r1, uint32_t& r2,
                                       uint32_t& r3, uint32_t addr) {
    asm volatile("ldmatrix.sync.aligned.m8n8.x4.shared.b16 {%0,%1,%2,%3}, [%4];"
                 : "=r"(r0), "=r"(r1), "=r"(r2), "=r"(r3) : "r"(addr));
}
__device__ __forceinline__ void mma16816(float* d, const uint32_t* a,
                                         uint32_t b0, uint32_t b1) {
    asm volatile(
        "mma.sync.aligned.m16n8k16.row.col.f32.f16.f16.f32 "
        "{%0,%1,%2,%3}, {%4,%5,%6,%7}, {%8,%9}, {%0,%1,%2,%3};"
        : "+f"(d[0]), "+f"(d[1]), "+f"(d[2]), "+f"(d[3])
        : "r"(a[0]), "r"(a[1]), "r"(a[2]), "r"(a[3]), "r"(b0), "r"(b1));
}

// ---------------------------------------------------------------------------
// Kernel 1: transpose x (B,I,T) fp32 -> (B,T,I) fp16 hi/lo
// ---------------------------------------------------------------------------
__global__ __launch_bounds__(256)
void conv_x(const float* __restrict__ x) {
    __shared__ float tile[32][33];
    const int b  = blockIdx.z;
    const int t0 = blockIdx.x * 32;
    const int i0 = blockIdx.y * 32;
    const int tx = threadIdx.x;
    const int ty = threadIdx.y;

    const float* src = x + ((size_t)b * I + i0) * T + t0;
#pragma unroll
    for (int k = 0; k < 4; ++k)
        tile[ty + k * 8][tx] = src[(size_t)(ty + k * 8) * T + tx];
    __syncthreads();

    __half* dh = g_Axh + ((size_t)b * T + t0) * I + i0;
    __half* dl = g_Axl + ((size_t)b * T + t0) * I + i0;
#pragma unroll
    for (int k = 0; k < 4; ++k) {
        const int r = ty + k * 8;
        const float v = tile[tx][r];
        const __half hi = __float2half(v);
        const __half lo = __float2half(v - __half2float(hi));
        dh[(size_t)r * I + tx] = hi;
        dl[(size_t)r * I + tx] = lo;
    }
}

// ---------------------------------------------------------------------------
// Kernel 2: transpose W (I,H) fp32 -> (H,I) fp16 hi/lo
// ---------------------------------------------------------------------------
__global__ __launch_bounds__(256)
void conv_w(const float* __restrict__ W) {
    __shared__ float tile[32][33];
    const int h0 = blockIdx.x * 32;
    const int i0 = blockIdx.y * 32;
    const int tx = threadIdx.x;
    const int ty = threadIdx.y;

    const float* src = W + ((size_t)i0) * H + h0;
#pragma unroll
    for (int k = 0; k < 4; ++k)
        tile[ty + k * 8][tx] = src[(size_t)(ty + k * 8) * H + tx];
    __syncthreads();

    __half* dh = g_Wh + ((size_t)h0) * I + i0;
    __half* dl = g_Wl + ((size_t)h0) * I + i0;
#pragma unroll
    for (int k = 0; k < 4; ++k) {
        const int r = ty + k * 8;
        const float v = tile[tx][r];
        const __half hi = __float2half(v);
        const __half lo = __float2half(v - __half2float(hi));
        dh[(size_t)r * I + tx] = hi;
        dl[(size_t)r * I + tx] = lo;
    }
}

// ---------------------------------------------------------------------------
// Kernel 3: hybrid GEMM, parity-correct role assignment.
// Classic placement maps bid and bid+148 to the SAME SM (occ=2). 148 is even,
// so role = bid&1 pairs same roles (round-6 bug). role = (bid>>7)&1 makes
// 86% of co-resident pairs mixed (fp32 + mma on one SM -> disjoint pipes).
// Even role: fp32 SGEMM, h in [0,512). Odd role: fp16 3-product MMA, h in
// [512,1024). 1024 CTAs per role, D tile 128x128.
// ---------------------------------------------------------------------------
constexpr int BM = 128, BN = 128;

// mma-path config
constexpr int KC = 32;
constexpr int STAGES = 4;
constexpr int NSTG = 3 * (I / KC);              // 48
constexpr int ROWE = KC + 8;                    // 40 (pad -> conflict-free ldmatrix)
constexpr int ROWB = ROWE * 2;                  // 80 bytes
constexpr int TILE_BYTES  = BM * ROWB;          // 10240
constexpr int STAGE_BYTES = 2 * TILE_BYTES;     // 20480
constexpr int SMEM_DYN = STAGES * STAGE_BYTES;  // 81920

// fp32-path config
constexpr int FK = 16;
constexpr int FTM = 8, FTN = 8;

__global__ __launch_bounds__(256, 2)
void gemm_hybrid(const float* __restrict__ x, const float* __restrict__ W) {
    extern __shared__ __align__(128) char smem[];
    const int tid  = threadIdx.x;
    const int bid  = blockIdx.x;
    const int role = (bid >> 7) & 1;                    // 128-bid blocks alternate
    const int q    = ((bid >> 8) << 7) | (bid & 127);   // rank within role: 0..1023
    const int hb   = q & 3;
    const int tb   = (q >> 2) & 3;
    const int b    = q >> 4;
    const int t0   = tb * BM;

    if (role == 0) {
        // ---------------- fp32 SGEMM, h0 in [0,512) ----------------
        const int h0 = hb * BN;
        float* As = (float*)smem;                       // [2][FK][BM]
        float* Bs = As + 2 * FK * BM;                   // [2][FK][BN]

        const float* Ab = x + (size_t)b * I * T + t0;   // (i,t): Ab[i*T+t]
        const float* Bb = W + h0;                       // (i,n): Bb[i*H+n]

        const int idx0 = tid, idx1 = tid + 256;
        const int ka0 = idx0 >> 5, ma0 = (idx0 & 31) << 2;
        const int ka1 = idx1 >> 5, ma1 = (idx1 & 31) << 2;

        float4 aR0 = *(const float4*)(Ab + (size_t)ka0 * T + ma0);
        float4 aR1 = *(const float4*)(Ab + (size_t)ka1 * T + ma1);
        float4 bR0 = *(const float4*)(Bb + (size_t)ka0 * H + ma0);
        float4 bR1 = *(const float4*)(Bb + (size_t)ka1 * H + ma1);
        *(float4*)&As[(0 * FK + ka0) * BM + ma0] = aR0;
        *(float4*)&As[(0 * FK + ka1) * BM + ma1] = aR1;
        *(float4*)&Bs[(0 * FK + ka0) * BN + ma0] = bR0;
        *(float4*)&Bs[(0 * FK + ka1) * BN + ma1] = bR1;
        __syncthreads();

        const int tx  = tid & 15;
        const int ty  = tid >> 4;
        const int tm0 = ty * FTM;
        const int tn0 = tx * FTN;

        float acc[FTM][FTN];
#pragma unroll
        for (int i = 0; i < FTM; ++i)
#pragma unroll
            for (int j = 0; j < FTN; ++j) acc[i][j] = 0.0f;

        constexpr int KT = I / FK;              // 32
        int p = 0;
        for (int kt = 0; kt < KT; ++kt) {
            if (kt + 1 < KT) {
                const float* An = Ab + (size_t)(kt + 1) * FK * T;
                const float* Bn = Bb + (size_t)(kt + 1) * FK * H;
                aR0 = *(const float4*)(An + (size_t)ka0 * T + ma0);
                aR1 = *(const float4*)(An + (size_t)ka1 * T + ma1);
                bR0 = *(const float4*)(Bn + (size_t)ka0 * H + ma0);
                bR1 = *(const float4*)(Bn + (size_t)ka1 * H + ma1);
            }
#pragma unroll
            for (int kk = 0; kk < FK; ++kk) {
                float a[FTM], bb[FTN];
                *(float4*)&a[0]  = *(const float4*)&As[(p * FK + kk) * BM + tm0];
                *(float4*)&a[4]  = *(const float4*)&As[(p * FK + kk) * BM + tm0 + 4];
                *(float4*)&bb[0] = *(const float4*)&Bs[(p * FK + kk) * BN + tn0];
                *(float4*)&bb[4] = *(const float4*)&Bs[(p * FK + kk) * BN + tn0 + 4];
#pragma unroll
                for (int i = 0; i < FTM; ++i)
#pragma unroll
                    for (int j = 0; j < FTN; ++j)
                        acc[i][j] += a[i] * bb[j];
            }
            if (kt + 1 < KT) {
                const int pq = p ^ 1;
                *(float4*)&As[(pq * FK + ka0) * BM + ma0] = aR0;
                *(float4*)&As[(pq * FK + ka1) * BM + ma1] = aR1;
                *(float4*)&Bs[(pq * FK + ka0) * BN + ma0] = bR0;
                *(float4*)&Bs[(pq * FK + ka1) * BN + ma1] = bR1;
                __syncthreads();
                p = pq;
            }
        }

#pragma unroll
        for (int i = 0; i < FTM; ++i) {
            const int t = t0 + tm0 + i;
            float* out = g_proj + ((size_t)t * B + b) * H + h0 + tn0;
            *(float4*)(out)     = make_float4(acc[i][0], acc[i][1], acc[i][2], acc[i][3]);
            *(float4*)(out + 4) = make_float4(acc[i][4], acc[i][5], acc[i][6], acc[i][7]);
        }
    } else {
        // ---------------- fp16 3-product MMA, h0 in [512,1024) ----------------
        const int h0 = 512 + hb * BN;
        const uint32_t sb = s2u(smem);
        const int warp = tid >> 5;
        const int lane = tid & 31;
        const int wm = warp & 1;
        const int wn = warp >> 1;

        const int r0 = tid >> 1;
        const int c0 = (tid * 2) & 3;
        const int c1 = c0 + 1;

        const __half* Ah = g_Axh + ((size_t)(b * T + t0)) * I;
        const __half* Al = g_Axl + ((size_t)(b * T + t0)) * I;
        const __half* Bh = g_Wh + ((size_t)h0) * I;
        const __half* Bl = g_Wl + ((size_t)h0) * I;

        auto load_stage = [&](int s) {
            const int ph = s >> 4;
            const int kc = s & 15;
            const size_t i0 = (size_t)kc * KC;
            const __half* Ap = (ph == 2 ? Al : Ah) + i0;   // hi,hi,lo
            const __half* Bp = (ph == 1 ? Bl : Bh) + i0;   // hi,lo,hi
            const uint32_t sA = sb + (s % STAGES) * STAGE_BYTES;
            const uint32_t sB = sA + TILE_BYTES;
            cp16(sA + r0 * ROWB + c0 * 16, Ap + (size_t)r0 * I + c0 * 8);
            cp16(sA + r0 * ROWB + c1 * 16, Ap + (size_t)r0 * I + c1 * 8);
            cp16(sB + r0 * ROWB + c0 * 16, Bp + (size_t)r0 * I + c0 * 8);
            cp16(sB + r0 * ROWB + c1 * 16, Bp + (size_t)r0 * I + c1 * 8);
        };

        load_stage(0); cp_commit();
        load_stage(1); cp_commit();
        load_stage(2); cp_commit();

        float acc[4][4][4];
#pragma unroll
        for (int mt = 0; mt < 4; ++mt)
#pragma unroll
            for (int nj = 0; nj < 4; ++nj)
#pragma unroll
                for (int r = 0; r < 4; ++r) acc[mt][nj][r] = 0.0f;

        const int a_row = (lane & 15);
        const int a_kh  = (lane >> 4) * 8;
        const int b_row = (lane & 7) + ((lane >> 4) << 3);
        const int b_kh  = ((lane >> 3) & 1) * 8;

        for (int s = 0; s < NSTG; ++s) {
            cp_wait<STAGES - 2>();
            __syncthreads();
            if (s + STAGES - 1 < NSTG) load_stage(s + STAGES - 1);
            cp_commit();

            const uint32_t sA = sb + (s % STAGES) * STAGE_BYTES;
            const uint32_t sB = sA + TILE_BYTES;

#pragma unroll
            for (int kk = 0; kk < KC; kk += 16) {
                uint32_t a[4][4], bb[2][4];
#pragma unroll
                for (int mt = 0; mt < 4; ++mt) {
                    const int m = wm * 64 + mt * 16 + a_row;
                    ldm_x4(a[mt][0], a[mt][1], a[mt][2], a[mt][3],
                           sA + m * ROWB + (kk + a_kh) * 2);
                }
#pragma unroll
                for (int nt = 0; nt < 2; ++nt) {
                    const int n = wn * 32 + nt * 16 + b_row;
                    ldm_x4(bb[nt][0], bb[nt][1], bb[nt][2], bb[nt][3],
                           sB + n * ROWB + (kk + b_kh) * 2);
                }
#pragma unroll
                for (int mt = 0; mt < 4; ++mt)
#pragma unroll
                    for (int nj = 0; nj < 4; ++nj) {
                        const int nt = nj >> 1;
                        const int hh = (nj & 1) * 2;
                        mma16816(acc[mt][nj], a[mt], bb[nt][hh], bb[nt][hh + 1]);
                    }
            }
            __syncthreads();
        }

#pragma unroll
        for (int mt = 0; mt < 4; ++mt) {
            const int tg = t0 + wm * 64 + mt * 16 + (lane >> 2);
#pragma unroll
            for (int nj = 0; nj < 4; ++nj) {
                const int h = h0 + wn * 32 + nj * 8 + (lane & 3) * 2;
                float* o0 = g_proj + ((size_t)tg * B + b) * H + h;
                float* o1 = g_proj + ((size_t)(tg + 8) * B + b) * H + h;
                *(float2*)o0 = make_float2(acc[mt][nj][0], acc[mt][nj][1]);
                *(float2*)o1 = make_float2(acc[mt][nj][2], acc[mt][nj][3]);
            }
        }
    }
}

// ---------------------------------------------------------------------------
// Kernel 4: sequential recurrence
// ---------------------------------------------------------------------------
__global__ __launch_bounds__(256)
void scan_kernel(const float* __restrict__ bias, float* __restrict__ out) {
    const int gid = blockIdx.x * blockDim.x + threadIdx.x;
    const int b = gid >> 10;
    const int h = gid & (H - 1);

    const float bv = __ldg(bias + h);
    const float* p = g_proj + (size_t)b * H + h;
    constexpr int STRIDE = B * H;
    constexpr int CH = 16;

    float hc = 0.0f, y = 0.0f;
    float buf[CH];
#pragma unroll
    for (int j = 0; j < CH; ++j) buf[j] = p[(size_t)j * STRIDE];

    for (int tt = 0; tt < T; tt += CH) {
        float nbuf[CH];
        if (tt + CH < T) {
            const float* pn = p + (size_t)(tt + CH) * STRIDE;
#pragma unroll
            for (int j = 0; j < CH; ++j) nbuf[j] = pn[(size_t)j * STRIDE];
        } else {
#pragma unroll
            for (int j = 0; j < CH; ++j) nbuf[j] = 0.0f;
        }
#pragma unroll
        for (int j = 0; j < CH; ++j) {
            hc = fmaxf(buf[j] + DECAY * hc * (1.0f - y), 0.0f);
            const float z = hc + bv;
            y = (z > 1.0f) ? z : 0.0f;
        }
#pragma unroll
        for (int j = 0; j < CH; ++j) buf[j] = nbuf[j];
    }
    out[gid] = y;
}

// ---------------------------------------------------------------------------
extern "C" void kernel_launch(void* const* d_in, const int* in_sizes, int n_in,
                              void* d_out, int out_size) {
    const float* x    = (const float*)d_in[0];  // (B, I, T)
    const float* W    = (const float*)d_in[1];  // (I, H)
    const float* bias = (const float*)d_in[2];  // (1, H)
    float* out        = (float*)d_out;          // (B, H)

    cudaFuncSetAttribute(gemm_hybrid, cudaFuncAttributeMaxDynamicSharedMemorySize,
                         SMEM_DYN);

    conv_x<<<dim3(T / 32, I / 32, B), dim3(32, 8)>>>(x);
    conv_w<<<dim3(H / 32, I / 32), dim3(32, 8)>>>(W);
    gemm_hybrid<<<2048, 256, SMEM_DYN>>>(x, W);
    scan_kernel<<<(B * H) / 256, 256>>>(bias, out);
}

// round 8
// speedup vs baseline: 1.4380x; 1.1705x over previous
#include <cuda_runtime.h>
#include <cuda_fp16.h>
#include <cstdint>

// ---------------------------------------------------------------------------
// Problem constants
// ---------------------------------------------------------------------------
constexpr int B = 64;
constexpr int I = 512;
constexpr int T = 512;
constexpr int H = 1024;
constexpr float DECAY = 0.8f;

// ---------------------------------------------------------------------------
// Device scratch
// ---------------------------------------------------------------------------
__device__ __half g_Ax[(size_t)B * T * I];          // fp16(x^T)        (b,t,i)
__device__ __half g_Wh[(size_t)H * I];              // fp16 hi of W^T-0.5 (h,i)
__device__ __half g_Wl[(size_t)H * I];              // fp16 lo of W^T-0.5
__device__ float  g_part[(size_t)B * 16 * T];       // partial rowsums
__device__ float  g_csum[(size_t)B * T];            // 0.5 * sum_i x[b,i,t]
__device__ float  g_proj[(size_t)T * B * H];        // proj (t, b, h)

// ---------------------------------------------------------------------------
// PTX helpers (plain compute_103 features only)
// ---------------------------------------------------------------------------
__device__ __forceinline__ uint32_t s2u(const void* p) {
    uint32_t a;
    asm("{ .reg .u64 t; cvta.to.shared.u64 t, %1; cvt.u32.u64 %0, t; }"
        : "=r"(a) : "l"(p));
    return a;
}
__device__ __forceinline__ void cp16(uint32_t dst, const void* src) {
    asm volatile("cp.async.cg.shared.global [%0], [%1], 16;" :: "r"(dst), "l"(src));
}
__device__ __forceinline__ void cp_commit() {
    asm volatile("cp.async.commit_group;" ::: "memory");
}
template <int N>
__device__ __forceinline__ void cp_wait() {
    asm volatile("cp.async.wait_group %0;" :: "n"(N) : "memory");
}
__device__ __forceinline__ void ldm_x4(uint32_t& r0, uint32_t& r1, uint32_t& r2,
                                       uint32_t& r3, uint32_t addr) {
    asm volatile("ldmatrix.sync.aligned.m8n8.x4.shared.b16 {%0,%1,%2,%3}, [%4];"
                 : "=r"(r0), "=r"(r1), "=r"(r2), "=r"(r3) : "r"(addr));
}
__device__ __forceinline__ void mma16816(float* d, const uint32_t* a,
                                         uint32_t b0, uint32_t b1) {
    asm volatile(
        "mma.sync.aligned.m16n8k16.row.col.f32.f16.f16.f32 "
        "{%0,%1,%2,%3}, {%4,%5,%6,%7}, {%8,%9}, {%0,%1,%2,%3};"
        : "+f"(d[0]), "+f"(d[1]), "+f"(d[2]), "+f"(d[3])
        : "r"(a[0]), "r"(a[1]), "r"(a[2]), "r"(a[3]), "r"(b0), "r"(b1));
}

// ---------------------------------------------------------------------------
// Kernel 1: transpose x (B,I,T) fp32 -> (B,T,I) fp16, + partial rowsums
// ---------------------------------------------------------------------------
__global__ __launch_bounds__(256)
void conv_x(const float* __restrict__ x) {
    __shared__ float tile[32][33];
    __shared__ float psum[8][32];
    const int b  = blockIdx.z;
    const int t0 = blockIdx.x * 32;
    const int i0 = blockIdx.y * 32;
    const int tx = threadIdx.x;
    const int ty = threadIdx.y;

    const float* src = x + ((size_t)b * I + i0) * T + t0;
#pragma unroll
    for (int k = 0; k < 4; ++k)
        tile[ty + k * 8][tx] = src[(size_t)(ty + k * 8) * T + tx];   // [i_loc][t_loc]
    __syncthreads();

    __half* dh = g_Ax + ((size_t)b * T + t0) * I + i0;
#pragma unroll
    for (int k = 0; k < 4; ++k) {
        const int r = ty + k * 8;
        dh[(size_t)r * I + tx] = __float2half(tile[tx][r]);
    }

    float s = 0.0f;
#pragma unroll
    for (int k = 0; k < 4; ++k) s += tile[ty * 4 + k][tx];
    psum[ty][tx] = s;
    __syncthreads();
    if (ty == 0) {
        float tot = 0.0f;
#pragma unroll
        for (int j = 0; j < 8; ++j) tot += psum[j][tx];
        g_part[((size_t)b * 16 + blockIdx.y) * T + t0 + tx] = tot;
    }
}

__global__ __launch_bounds__(256)
void reduce_csum() {
    const int gid = blockIdx.x * blockDim.x + threadIdx.x;
    const int b = gid >> 9;
    const int t = gid & (T - 1);
    float s = 0.0f;
#pragma unroll
    for (int it = 0; it < 16; ++it)
        s += g_part[((size_t)b * 16 + it) * T + t];
    g_csum[(size_t)b * T + t] = 0.5f * s;
}

// ---------------------------------------------------------------------------
// Kernel 2: transpose W (I,H) fp32 -> (H,I), W-0.5 split into fp16 hi/lo
// ---------------------------------------------------------------------------
__global__ __launch_bounds__(256)
void conv_w(const float* __restrict__ W) {
    __shared__ float tile[32][33];
    const int h0 = blockIdx.x * 32;
    const int i0 = blockIdx.y * 32;
    const int tx = threadIdx.x;
    const int ty = threadIdx.y;

    const float* src = W + ((size_t)i0) * H + h0;
#pragma unroll
    for (int k = 0; k < 4; ++k)
        tile[ty + k * 8][tx] = src[(size_t)(ty + k * 8) * H + tx];
    __syncthreads();

    __half* dh = g_Wh + ((size_t)h0) * I + i0;
    __half* dl = g_Wl + ((size_t)h0) * I + i0;
#pragma unroll
    for (int k = 0; k < 4; ++k) {
        const int r = ty + k * 8;
        const float v = tile[tx][r] - 0.5f;
        const __half hi = __float2half(v);
        const __half lo = __float2half(v - __half2float(hi));
        dh[(size_t)r * I + tx] = hi;
        dl[(size_t)r * I + tx] = lo;
    }
}

// ---------------------------------------------------------------------------
// Kernel 3: hybrid GEMM, rebalanced 3/8 fp32 : 5/8 mma(2-product).
// role: (bid&7)<3 -> fp32 (h in [0,384)); else mma (h in [384,1024)).
// With classic placement pairing (bid, bid+148): (bid+148)&7 = (bid+4)&7, so
// 6/8 of co-resident pairs are mixed-role.
// mma: p = x16 * (Whi+Wlo) + 0.5*rowsum(x)_fp32; err ~6.4e-4 on those cols.
// ---------------------------------------------------------------------------
constexpr int BM = 128, BN = 128;

// mma-path config: 2 product phases x 16 k-chunks = 32 stages
constexpr int KC = 32;
constexpr int STAGES = 4;
constexpr int NSTG = 2 * (I / KC);              // 32
constexpr int ROWE = KC + 8;
constexpr int ROWB = ROWE * 2;                  // 80 bytes
constexpr int TILE_BYTES  = BM * ROWB;          // 10240
constexpr int STAGE_BYTES = 2 * TILE_BYTES;     // 20480
constexpr int SMEM_DYN = STAGES * STAGE_BYTES;  // 81920

// fp32-path config
constexpr int FK = 16;
constexpr int FTM = 8, FTN = 8;

__global__ __launch_bounds__(256, 2)
void gemm_hybrid(const float* __restrict__ x, const float* __restrict__ W) {
    extern __shared__ __align__(128) char smem[];
    const int tid = threadIdx.x;
    const int bid = blockIdx.x;
    const int sub = bid & 7;
    const bool is_fp32 = sub < 3;

    if (is_fp32) {
        // ---------------- fp32 SGEMM, h0 in [0,384) ----------------
        const int q  = (bid >> 3) * 3 + sub;            // 0..767
        const int hb = q % 3;
        const int r  = q / 3;
        const int tb = r & 3;
        const int b  = r >> 2;
        const int t0 = tb * BM;
        const int h0 = hb * BN;

        float* As = (float*)smem;
        float* Bs = As + 2 * FK * BM;

        const float* Ab = x + (size_t)b * I * T + t0;
        const float* Bb = W + h0;

        const int idx0 = tid, idx1 = tid + 256;
        const int ka0 = idx0 >> 5, ma0 = (idx0 & 31) << 2;
        const int ka1 = idx1 >> 5, ma1 = (idx1 & 31) << 2;

        float4 aR0 = *(const float4*)(Ab + (size_t)ka0 * T + ma0);
        float4 aR1 = *(const float4*)(Ab + (size_t)ka1 * T + ma1);
        float4 bR0 = *(const float4*)(Bb + (size_t)ka0 * H + ma0);
        float4 bR1 = *(const float4*)(Bb + (size_t)ka1 * H + ma1);
        *(float4*)&As[(0 * FK + ka0) * BM + ma0] = aR0;
        *(float4*)&As[(0 * FK + ka1) * BM + ma1] = aR1;
        *(float4*)&Bs[(0 * FK + ka0) * BN + ma0] = bR0;
        *(float4*)&Bs[(0 * FK + ka1) * BN + ma1] = bR1;
        __syncthreads();

        const int tx  = tid & 15;
        const int ty  = tid >> 4;
        const int tm0 = ty * FTM;
        const int tn0 = tx * FTN;

        float acc[FTM][FTN];
#pragma unroll
        for (int i = 0; i < FTM; ++i)
#pragma unroll
            for (int j = 0; j < FTN; ++j) acc[i][j] = 0.0f;

        constexpr int KT = I / FK;
        int p = 0;
        for (int kt = 0; kt < KT; ++kt) {
            if (kt + 1 < KT) {
                const float* An = Ab + (size_t)(kt + 1) * FK * T;
                const float* Bn = Bb + (size_t)(kt + 1) * FK * H;
                aR0 = *(const float4*)(An + (size_t)ka0 * T + ma0);
                aR1 = *(const float4*)(An + (size_t)ka1 * T + ma1);
                bR0 = *(const float4*)(Bn + (size_t)ka0 * H + ma0);
                bR1 = *(const float4*)(Bn + (size_t)ka1 * H + ma1);
            }
#pragma unroll
            for (int kk = 0; kk < FK; ++kk) {
                float a[FTM], bb[FTN];
                *(float4*)&a[0]  = *(const float4*)&As[(p * FK + kk) * BM + tm0];
                *(float4*)&a[4]  = *(const float4*)&As[(p * FK + kk) * BM + tm0 + 4];
                *(float4*)&bb[0] = *(const float4*)&Bs[(p * FK + kk) * BN + tn0];
                *(float4*)&bb[4] = *(const float4*)&Bs[(p * FK + kk) * BN + tn0 + 4];
#pragma unroll
                for (int i = 0; i < FTM; ++i)
#pragma unroll
                    for (int j = 0; j < FTN; ++j)
                        acc[i][j] += a[i] * bb[j];
            }
            if (kt + 1 < KT) {
                const int pq = p ^ 1;
                *(float4*)&As[(pq * FK + ka0) * BM + ma0] = aR0;
                *(float4*)&As[(pq * FK + ka1) * BM + ma1] = aR1;
                *(float4*)&Bs[(pq * FK + ka0) * BN + ma0] = bR0;
                *(float4*)&Bs[(pq * FK + ka1) * BN + ma1] = bR1;
                __syncthreads();
                p = pq;
            }
        }

#pragma unroll
        for (int i = 0; i < FTM; ++i) {
            const int t = t0 + tm0 + i;
            float* out = g_proj + ((size_t)t * B + b) * H + h0 + tn0;
            *(float4*)(out)     = make_float4(acc[i][0], acc[i][1], acc[i][2], acc[i][3]);
            *(float4*)(out + 4) = make_float4(acc[i][4], acc[i][5], acc[i][6], acc[i][7]);
        }
    } else {
        // -------- fp16 2-product MMA, h0 in [384,1024) --------
        const int q  = (bid >> 3) * 5 + (sub - 3);      // 0..1279
        const int hb = q % 5;
        const int r  = q / 5;
        const int tb = r & 3;
        const int b  = r >> 2;
        const int t0 = tb * BM;
        const int h0 = 384 + hb * BN;

        const uint32_t sb = s2u(smem);
        const int warp = tid >> 5;
        const int lane = tid & 31;
        const int wm = warp & 1;
        const int wn = warp >> 1;

        const int r0 = tid >> 1;
        const int c0 = (tid * 2) & 3;
        const int c1 = c0 + 1;

        const __half* Ab = g_Ax + ((size_t)(b * T + t0)) * I;
        const __half* Bh = g_Wh + ((size_t)h0) * I;
        const __half* Bl = g_Wl + ((size_t)h0) * I;

        auto load_stage = [&](int s) {
            const int ph = s >> 4;                      // 0: Whi, 1: Wlo
            const int kc = s & 15;
            const size_t i0 = (size_t)kc * KC;
            const __half* Ap = Ab + i0;
            const __half* Bp = (ph ? Bl : Bh) + i0;
            const uint32_t sA = sb + (s % STAGES) * STAGE_BYTES;
            const uint32_t sB = sA + TILE_BYTES;
            cp16(sA + r0 * ROWB + c0 * 16, Ap + (size_t)r0 * I + c0 * 8);
            cp16(sA + r0 * ROWB + c1 * 16, Ap + (size_t)r0 * I + c1 * 8);
            cp16(sB + r0 * ROWB + c0 * 16, Bp + (size_t)r0 * I + c0 * 8);
            cp16(sB + r0 * ROWB + c1 * 16, Bp + (size_t)r0 * I + c1 * 8);
        };

        load_stage(0); cp_commit();
        load_stage(1); cp_commit();
        load_stage(2); cp_commit();

        float acc[4][4][4];
#pragma unroll
        for (int mt = 0; mt < 4; ++mt)
#pragma unroll
            for (int nj = 0; nj < 4; ++nj)
#pragma unroll
                for (int rr = 0; rr < 4; ++rr) acc[mt][nj][rr] = 0.0f;

        const int a_row = (lane & 15);
        const int a_kh  = (lane >> 4) * 8;
        const int b_row = (lane & 7) + ((lane >> 4) << 3);
        const int b_kh  = ((lane >> 3) & 1) * 8;

        for (int s = 0; s < NSTG; ++s) {
            cp_wait<STAGES - 2>();
            __syncthreads();
            if (s + STAGES - 1 < NSTG) load_stage(s + STAGES - 1);
            cp_commit();

            const uint32_t sA = sb + (s % STAGES) * STAGE_BYTES;
            const uint32_t sB = sA + TILE_BYTES;

#pragma unroll
            for (int kk = 0; kk < KC; kk += 16) {
                uint32_t a[4][4], bb[2][4];
#pragma unroll
                for (int mt = 0; mt < 4; ++mt) {
                    const int m = wm * 64 + mt * 16 + a_row;
                    ldm_x4(a[mt][0], a[mt][1], a[mt][2], a[mt][3],
                           sA + m * ROWB + (kk + a_kh) * 2);
                }
#pragma unroll
                for (int nt = 0; nt < 2; ++nt) {
                    const int n = wn * 32 + nt * 16 + b_row;
                    ldm_x4(bb[nt][0], bb[nt][1], bb[nt][2], bb[nt][3],
                           sB + n * ROWB + (kk + b_kh) * 2);
                }
#pragma unroll
                for (int mt = 0; mt < 4; ++mt)
#pragma unroll
                    for (int nj = 0; nj < 4; ++nj) {
                        const int nt = nj >> 1;
                        const int hh = (nj & 1) * 2;
                        mma16816(acc[mt][nj], a[mt], bb[nt][hh], bb[nt][hh + 1]);
                    }
            }
            __syncthreads();
        }

        // Epilogue: add 0.5*rowsum(x) (exact fp32), store proj
#pragma unroll
        for (int mt = 0; mt < 4; ++mt) {
            const int tg = t0 + wm * 64 + mt * 16 + (lane >> 2);
            const float cc0 = g_csum[(size_t)b * T + tg];
            const float cc1 = g_csum[(size_t)b * T + tg + 8];
#pragma unroll
            for (int nj = 0; nj < 4; ++nj) {
                const int h = h0 + wn * 32 + nj * 8 + (lane & 3) * 2;
                float* o0 = g_proj + ((size_t)tg * B + b) * H + h;
                float* o1 = g_proj + ((size_t)(tg + 8) * B + b) * H + h;
                *(float2*)o0 = make_float2(acc[mt][nj][0] + cc0, acc[mt][nj][1] + cc0);
                *(float2*)o1 = make_float2(acc[mt][nj][2] + cc1, acc[mt][nj][3] + cc1);
            }
        }
    }
}

// ---------------------------------------------------------------------------
// Kernel 4: sequential recurrence
// ---------------------------------------------------------------------------
__global__ __launch_bounds__(256)
void scan_kernel(const float* __restrict__ bias, float* __restrict__ out) {
    const int gid = blockIdx.x * blockDim.x + threadIdx.x;
    const int b = gid >> 10;
    const int h = gid & (H - 1);

    const float bv = __ldg(bias + h);
    const float* p = g_proj + (size_t)b * H + h;
    constexpr int STRIDE = B * H;
    constexpr int CH = 16;

    float hc = 0.0f, y = 0.0f;
    float buf[CH];
#pragma unroll
    for (int j = 0; j < CH; ++j) buf[j] = p[(size_t)j * STRIDE];

    for (int tt = 0; tt < T; tt += CH) {
        float nbuf[CH];
        if (tt + CH < T) {
            const float* pn = p + (size_t)(tt + CH) * STRIDE;
#pragma unroll
            for (int j = 0; j < CH; ++j) nbuf[j] = pn[(size_t)j * STRIDE];
        } else {
#pragma unroll
            for (int j = 0; j < CH; ++j) nbuf[j] = 0.0f;
        }
#pragma unroll
        for (int j = 0; j < CH; ++j) {
            hc = fmaxf(buf[j] + DECAY * hc * (1.0f - y), 0.0f);
            const float z = hc + bv;
            y = (z > 1.0f) ? z : 0.0f;
        }
#pragma unroll
        for (int j = 0; j < CH; ++j) buf[j] = nbuf[j];
    }
    out[gid] = y;
}

// ---------------------------------------------------------------------------
extern "C" void kernel_launch(void* const* d_in, const int* in_sizes, int n_in,
                              void* d_out, int out_size) {
    const float* x    = (const float*)d_in[0];  // (B, I, T)
    const float* W    = (const float*)d_in[1];  // (I, H)
    const float* bias = (const float*)d_in[2];  // (1, H)
    float* out        = (float*)d_out;          // (B, H)

    cudaFuncSetAttribute(gemm_hybrid, cudaFuncAttributeMaxDynamicSharedMemorySize,
                         SMEM_DYN);

    conv_x<<<dim3(T / 32, I / 32, B), dim3(32, 8)>>>(x);
    reduce_csum<<<(B * T) / 256, 256>>>();
    conv_w<<<dim3(H / 32, I / 32), dim3(32, 8)>>>(W);
    gemm_hybrid<<<2048, 256, SMEM_DYN>>>(x, W);
    scan_kernel<<<(B * H) / 256, 256>>>(bias, out);
}

// round 9
// speedup vs baseline: 1.6332x; 1.1358x over previous
#include <cuda_runtime.h>
#include <cuda_fp16.h>
#include <cstdint>

// ---------------------------------------------------------------------------
// Problem constants
// ---------------------------------------------------------------------------
constexpr int B = 64;
constexpr int I = 512;
constexpr int T = 512;
constexpr int H = 1024;
constexpr float DECAY = 0.8f;

// ---------------------------------------------------------------------------
// Device scratch
// ---------------------------------------------------------------------------
__device__ __half g_Ax[(size_t)B * T * I];          // fp16(x^T)          (b,t,i)
__device__ __half g_Wh[(size_t)H * I];              // fp16 hi of W^T-0.5 (h,i)
__device__ __half g_Wl[(size_t)H * I];              // fp16 lo of W^T-0.5
__device__ float  g_part[(size_t)B * 16 * T];       // partial rowsums
__device__ float  g_csum[(size_t)B * T];            // 0.5 * sum_i x[b,i,t]
__device__ float  g_proj[(size_t)T * B * H];        // proj (t, b, h)

// ---------------------------------------------------------------------------
// PTX helpers (plain compute_103 features only; f32x2 is sm_100-family PTX,
// no arch-specific 'a' suffix required)
// ---------------------------------------------------------------------------
__device__ __forceinline__ uint32_t s2u(const void* p) {
    uint32_t a;
    asm("{ .reg .u64 t; cvta.to.shared.u64 t, %1; cvt.u32.u64 %0, t; }"
        : "=r"(a) : "l"(p));
    return a;
}
__device__ __forceinline__ void cp16(uint32_t dst, const void* src) {
    asm volatile("cp.async.cg.shared.global [%0], [%1], 16;" :: "r"(dst), "l"(src));
}
__device__ __forceinline__ void cp_commit() {
    asm volatile("cp.async.commit_group;" ::: "memory");
}
template <int N>
__device__ __forceinline__ void cp_wait() {
    asm volatile("cp.async.wait_group %0;" :: "n"(N) : "memory");
}
__device__ __forceinline__ void ldm_x4(uint32_t& r0, uint32_t& r1, uint32_t& r2,
                                       uint32_t& r3, uint32_t addr) {
    asm volatile("ldmatrix.sync.aligned.m8n8.x4.shared.b16 {%0,%1,%2,%3}, [%4];"
                 : "=r"(r0), "=r"(r1), "=r"(r2), "=r"(r3) : "r"(addr));
}
__device__ __forceinline__ void mma16816(float* d, const uint32_t* a,
                                         uint32_t b0, uint32_t b1) {
    asm volatile(
        "mma.sync.aligned.m16n8k16.row.col.f32.f16.f16.f32 "
        "{%0,%1,%2,%3}, {%4,%5,%6,%7}, {%8,%9}, {%0,%1,%2,%3};"
        : "+f"(d[0]), "+f"(d[1]), "+f"(d[2]), "+f"(d[3])
        : "r"(a[0]), "r"(a[1]), "r"(a[2]), "r"(a[3]), "r"(b0), "r"(b1));
}
// packed fp32 pair ops
__device__ __forceinline__ void fma2(uint64_t& d, uint64_t a, uint64_t b) {
    asm("fma.rn.f32x2 %0, %1, %2, %0;" : "+l"(d) : "l"(a), "l"(b));
}
__device__ __forceinline__ uint64_t pack2(float v) {
    uint64_t r; asm("mov.b64 %0, {%1, %1};" : "=l"(r) : "f"(v)); return r;
}
__device__ __forceinline__ void unpack2(uint64_t p, float& lo, float& hi) {
    asm("mov.b64 {%0, %1}, %2;" : "=f"(lo), "=f"(hi) : "l"(p));
}

// ---------------------------------------------------------------------------
// Kernel 1: transpose x (B,I,T) fp32 -> (B,T,I) fp16, + partial rowsums
// ---------------------------------------------------------------------------
__global__ __launch_bounds__(256)
void conv_x(const float* __restrict__ x) {
    __shared__ float tile[32][33];
    __shared__ float psum[8][32];
    const int b  = blockIdx.z;
    const int t0 = blockIdx.x * 32;
    const int i0 = blockIdx.y * 32;
    const int tx = threadIdx.x;
    const int ty = threadIdx.y;

    const float* src = x + ((size_t)b * I + i0) * T + t0;
#pragma unroll
    for (int k = 0; k < 4; ++k)
        tile[ty + k * 8][tx] = src[(size_t)(ty + k * 8) * T + tx];
    __syncthreads();

    __half* dh = g_Ax + ((size_t)b * T + t0) * I + i0;
#pragma unroll
    for (int k = 0; k < 4; ++k) {
        const int r = ty + k * 8;
        dh[(size_t)r * I + tx] = __float2half(tile[tx][r]);
    }

    float s = 0.0f;
#pragma unroll
    for (int k = 0; k < 4; ++k) s += tile[ty * 4 + k][tx];
    psum[ty][tx] = s;
    __syncthreads();
    if (ty == 0) {
        float tot = 0.0f;
#pragma unroll
        for (int j = 0; j < 8; ++j) tot += psum[j][tx];
        g_part[((size_t)b * 16 + blockIdx.y) * T + t0 + tx] = tot;
    }
}

__global__ __launch_bounds__(256)
void reduce_csum() {
    const int gid = blockIdx.x * blockDim.x + threadIdx.x;
    const int b = gid >> 9;
    const int t = gid & (T - 1);
    float s = 0.0f;
#pragma unroll
    for (int it = 0; it < 16; ++it)
        s += g_part[((size_t)b * 16 + it) * T + t];
    g_csum[(size_t)b * T + t] = 0.5f * s;
}

// ---------------------------------------------------------------------------
// Kernel 2: transpose W (I,H) fp32 -> (H,I), W-0.5 split into fp16 hi/lo
// ---------------------------------------------------------------------------
__global__ __launch_bounds__(256)
void conv_w(const float* __restrict__ W) {
    __shared__ float tile[32][33];
    const int h0 = blockIdx.x * 32;
    const int i0 = blockIdx.y * 32;
    const int tx = threadIdx.x;
    const int ty = threadIdx.y;

    const float* src = W + ((size_t)i0) * H + h0;
#pragma unroll
    for (int k = 0; k < 4; ++k)
        tile[ty + k * 8][tx] = src[(size_t)(ty + k * 8) * H + tx];
    __syncthreads();

    __half* dh = g_Wh + ((size_t)h0) * I + i0;
    __half* dl = g_Wl + ((size_t)h0) * I + i0;
#pragma unroll
    for (int k = 0; k < 4; ++k) {
        const int r = ty + k * 8;
        const float v = tile[tx][r] - 0.5f;
        const __half hi = __float2half(v);
        const __half lo = __float2half(v - __half2float(hi));
        dh[(size_t)r * I + tx] = hi;
        dl[(size_t)r * I + tx] = lo;
    }
}

// ---------------------------------------------------------------------------
// Kernel 3: hybrid GEMM, 2/8 fp32 : 6/8 mma(2-product), L1-balanced.
// role: (bid&7)<2 -> fp32 (h in [0,256)); else mma (h in [256,1024)).
// (bid+148)&7 = (bid+4)&7, so every fp32 CTA co-resides with an mma CTA.
// fp32 inner loop uses packed fma.rn.f32x2 (halves FFMA issue slots).
// ---------------------------------------------------------------------------
constexpr int BM = 128, BN = 128;

// mma-path config: 2 product phases x 16 k-chunks = 32 stages
constexpr int KC = 32;
constexpr int STAGES = 4;
constexpr int NSTG = 2 * (I / KC);              // 32
constexpr int ROWE = KC + 8;
constexpr int ROWB = ROWE * 2;                  // 80 bytes
constexpr int TILE_BYTES  = BM * ROWB;          // 10240
constexpr int STAGE_BYTES = 2 * TILE_BYTES;     // 20480
constexpr int SMEM_DYN = STAGES * STAGE_BYTES;  // 81920

// fp32-path config
constexpr int FK = 16;
constexpr int FTM = 8, FTN = 8;

__global__ __launch_bounds__(256, 2)
void gemm_hybrid(const float* __restrict__ x, const float* __restrict__ W) {
    extern __shared__ __align__(128) char smem[];
    const int tid = threadIdx.x;
    const int bid = blockIdx.x;
    const int sub = bid & 7;
    const bool is_fp32 = sub < 2;

    if (is_fp32) {
        // ---------------- fp32 SGEMM (f32x2), h0 in [0,256) ----------------
        const int q  = (bid >> 3) * 2 + sub;            // 0..511
        const int hb = q & 1;
        const int r  = q >> 1;
        const int tb = r & 3;
        const int b  = r >> 2;
        const int t0 = tb * BM;
        const int h0 = hb * BN;

        float* As = (float*)smem;
        float* Bs = As + 2 * FK * BM;

        const float* Ab = x + (size_t)b * I * T + t0;
        const float* Bb = W + h0;

        const int idx0 = tid, idx1 = tid + 256;
        const int ka0 = idx0 >> 5, ma0 = (idx0 & 31) << 2;
        const int ka1 = idx1 >> 5, ma1 = (idx1 & 31) << 2;

        float4 aR0 = *(const float4*)(Ab + (size_t)ka0 * T + ma0);
        float4 aR1 = *(const float4*)(Ab + (size_t)ka1 * T + ma1);
        float4 bR0 = *(const float4*)(Bb + (size_t)ka0 * H + ma0);
        float4 bR1 = *(const float4*)(Bb + (size_t)ka1 * H + ma1);
        *(float4*)&As[(0 * FK + ka0) * BM + ma0] = aR0;
        *(float4*)&As[(0 * FK + ka1) * BM + ma1] = aR1;
        *(float4*)&Bs[(0 * FK + ka0) * BN + ma0] = bR0;
        *(float4*)&Bs[(0 * FK + ka1) * BN + ma1] = bR1;
        __syncthreads();

        const int tx  = tid & 15;
        const int ty  = tid >> 4;
        const int tm0 = ty * FTM;
        const int tn0 = tx * FTN;

        uint64_t acc2[FTM][FTN / 2];
#pragma unroll
        for (int i = 0; i < FTM; ++i)
#pragma unroll
            for (int j = 0; j < FTN / 2; ++j) acc2[i][j] = 0ull;

        constexpr int KT = I / FK;
        int p = 0;
        for (int kt = 0; kt < KT; ++kt) {
            if (kt + 1 < KT) {
                const float* An = Ab + (size_t)(kt + 1) * FK * T;
                const float* Bn = Bb + (size_t)(kt + 1) * FK * H;
                aR0 = *(const float4*)(An + (size_t)ka0 * T + ma0);
                aR1 = *(const float4*)(An + (size_t)ka1 * T + ma1);
                bR0 = *(const float4*)(Bn + (size_t)ka0 * H + ma0);
                bR1 = *(const float4*)(Bn + (size_t)ka1 * H + ma1);
            }
#pragma unroll
            for (int kk = 0; kk < FK; ++kk) {
                float a[FTM];
                uint64_t bb2[FTN / 2];
                *(float4*)&a[0] = *(const float4*)&As[(p * FK + kk) * BM + tm0];
                *(float4*)&a[4] = *(const float4*)&As[(p * FK + kk) * BM + tm0 + 4];
                *(ulonglong2*)&bb2[0] =
                    *(const ulonglong2*)&Bs[(p * FK + kk) * BN + tn0];
                *(ulonglong2*)&bb2[2] =
                    *(const ulonglong2*)&Bs[(p * FK + kk) * BN + tn0 + 4];
#pragma unroll
                for (int i = 0; i < FTM; ++i) {
                    const uint64_t aa = pack2(a[i]);
#pragma unroll
                    for (int j = 0; j < FTN / 2; ++j)
                        fma2(acc2[i][j], aa, bb2[j]);
                }
            }
            if (kt + 1 < KT) {
                const int pq = p ^ 1;
                *(float4*)&As[(pq * FK + ka0) * BM + ma0] = aR0;
                *(float4*)&As[(pq * FK + ka1) * BM + ma1] = aR1;
                *(float4*)&Bs[(pq * FK + ka0) * BN + ma0] = bR0;
                *(float4*)&Bs[(pq * FK + ka1) * BN + ma1] = bR1;
                __syncthreads();
                p = pq;
            }
        }

#pragma unroll
        for (int i = 0; i < FTM; ++i) {
            const int t = t0 + tm0 + i;
            float v[FTN];
#pragma unroll
            for (int j = 0; j < FTN / 2; ++j)
                unpack2(acc2[i][j], v[2 * j], v[2 * j + 1]);
            float* out = g_proj + ((size_t)t * B + b) * H + h0 + tn0;
            *(float4*)(out)     = make_float4(v[0], v[1], v[2], v[3]);
            *(float4*)(out + 4) = make_float4(v[4], v[5], v[6], v[7]);
        }
    } else {
        // -------- fp16 2-product MMA, h0 in [256,1024) --------
        const int q  = (bid >> 3) * 6 + (sub - 2);      // 0..1535
        const int hb = q % 6;
        const int r  = q / 6;
        const int tb = r & 3;
        const int b  = r >> 2;
        const int t0 = tb * BM;
        const int h0 = 256 + hb * BN;

        const uint32_t sb = s2u(smem);
        const int warp = tid >> 5;
        const int lane = tid & 31;
        const int wm = warp & 1;
        const int wn = warp >> 1;

        const int r0 = tid >> 1;
        const int c0 = (tid * 2) & 3;
        const int c1 = c0 + 1;

        const __half* Ab = g_Ax + ((size_t)(b * T + t0)) * I;
        const __half* Bh = g_Wh + ((size_t)h0) * I;
        const __half* Bl = g_Wl + ((size_t)h0) * I;

        auto load_stage = [&](int s) {
            const int ph = s >> 4;                      // 0: Whi, 1: Wlo
            const int kc = s & 15;
            const size_t i0 = (size_t)kc * KC;
            const __half* Ap = Ab + i0;
            const __half* Bp = (ph ? Bl : Bh) + i0;
            const uint32_t sA = sb + (s % STAGES) * STAGE_BYTES;
            const uint32_t sB = sA + TILE_BYTES;
            cp16(sA + r0 * ROWB + c0 * 16, Ap + (size_t)r0 * I + c0 * 8);
            cp16(sA + r0 * ROWB + c1 * 16, Ap + (size_t)r0 * I + c1 * 8);
            cp16(sB + r0 * ROWB + c0 * 16, Bp + (size_t)r0 * I + c0 * 8);
            cp16(sB + r0 * ROWB + c1 * 16, Bp + (size_t)r0 * I + c1 * 8);
        };

        load_stage(0); cp_commit();
        load_stage(1); cp_commit();
        load_stage(2); cp_commit();

        float acc[4][4][4];
#pragma unroll
        for (int mt = 0; mt < 4; ++mt)
#pragma unroll
            for (int nj = 0; nj < 4; ++nj)
#pragma unroll
                for (int rr = 0; rr < 4; ++rr) acc[mt][nj][rr] = 0.0f;

        const int a_row = (lane & 15);
        const int a_kh  = (lane >> 4) * 8;
        const int b_row = (lane & 7) + ((lane >> 4) << 3);
        const int b_kh  = ((lane >> 3) & 1) * 8;

        for (int s = 0; s < NSTG; ++s) {
            cp_wait<STAGES - 2>();
            __syncthreads();
            if (s + STAGES - 1 < NSTG) load_stage(s + STAGES - 1);
            cp_commit();

            const uint32_t sA = sb + (s % STAGES) * STAGE_BYTES;
            const uint32_t sB = sA + TILE_BYTES;

#pragma unroll
            for (int kk = 0; kk < KC; kk += 16) {
                uint32_t a[4][4], bb[2][4];
#pragma unroll
                for (int mt = 0; mt < 4; ++mt) {
                    const int m = wm * 64 + mt * 16 + a_row;
                    ldm_x4(a[mt][0], a[mt][1], a[mt][2], a[mt][3],
                           sA + m * ROWB + (kk + a_kh) * 2);
                }
#pragma unroll
                for (int nt = 0; nt < 2; ++nt) {
                    const int n = wn * 32 + nt * 16 + b_row;
                    ldm_x4(bb[nt][0], bb[nt][1], bb[nt][2], bb[nt][3],
                           sB + n * ROWB + (kk + b_kh) * 2);
                }
#pragma unroll
                for (int mt = 0; mt < 4; ++mt)
#pragma unroll
                    for (int nj = 0; nj < 4; ++nj) {
                        const int nt = nj >> 1;
                        const int hh = (nj & 1) * 2;
                        mma16816(acc[mt][nj], a[mt], bb[nt][hh], bb[nt][hh + 1]);
                    }
            }
            __syncthreads();
        }

        // Epilogue: add 0.5*rowsum(x) (exact fp32), store proj
#pragma unroll
        for (int mt = 0; mt < 4; ++mt) {
            const int tg = t0 + wm * 64 + mt * 16 + (lane >> 2);
            const float cc0 = g_csum[(size_t)b * T + tg];
            const float cc1 = g_csum[(size_t)b * T + tg + 8];
#pragma unroll
            for (int nj = 0; nj < 4; ++nj) {
                const int h = h0 + wn * 32 + nj * 8 + (lane & 3) * 2;
                float* o0 = g_proj + ((size_t)tg * B + b) * H + h;
                float* o1 = g_proj + ((size_t)(tg + 8) * B + b) * H + h;
                *(float2*)o0 = make_float2(acc[mt][nj][0] + cc0, acc[mt][nj][1] + cc0);
                *(float2*)o1 = make_float2(acc[mt][nj][2] + cc1, acc[mt][nj][3] + cc1);
            }
        }
    }
}

// ---------------------------------------------------------------------------
// Kernel 4: sequential recurrence
// ---------------------------------------------------------------------------
__global__ __launch_bounds__(256)
void scan_kernel(const float* __restrict__ bias, float* __restrict__ out) {
    const int gid = blockIdx.x * blockDim.x + threadIdx.x;
    const int b = gid >> 10;
    const int h = gid & (H - 1);

    const float bv = __ldg(bias + h);
    const float* p = g_proj + (size_t)b * H + h;
    constexpr int STRIDE = B * H;
    constexpr int CH = 16;

    float hc = 0.0f, y = 0.0f;
    float buf[CH];
#pragma unroll
    for (int j = 0; j < CH; ++j) buf[j] = p[(size_t)j * STRIDE];

    for (int tt = 0; tt < T; tt += CH) {
        float nbuf[CH];
        if (tt + CH < T) {
            const float* pn = p + (size_t)(tt + CH) * STRIDE;
#pragma unroll
            for (int j = 0; j < CH; ++j) nbuf[j] = pn[(size_t)j * STRIDE];
        } else {
#pragma unroll
            for (int j = 0; j < CH; ++j) nbuf[j] = 0.0f;
        }
#pragma unroll
        for (int j = 0; j < CH; ++j) {
            hc = fmaxf(buf[j] + DECAY * hc * (1.0f - y), 0.0f);
            const float z = hc + bv;
            y = (z > 1.0f) ? z : 0.0f;
        }
#pragma unroll
        for (int j = 0; j < CH; ++j) buf[j] = nbuf[j];
    }
    out[gid] = y;
}

// ---------------------------------------------------------------------------
extern "C" void kernel_launch(void* const* d_in, const int* in_sizes, int n_in,
                              void* d_out, int out_size) {
    const float* x    = (const float*)d_in[0];  // (B, I, T)
    const float* W    = (const float*)d_in[1];  // (I, H)
    const float* bias = (const float*)d_in[2];  // (1, H)
    float* out        = (float*)d_out;          // (B, H)

    cudaFuncSetAttribute(gemm_hybrid, cudaFuncAttributeMaxDynamicSharedMemorySize,
                         SMEM_DYN);

    conv_x<<<dim3(T / 32, I / 32, B), dim3(32, 8)>>>(x);
    reduce_csum<<<(B * T) / 256, 256>>>();
    conv_w<<<dim3(H / 32, I / 32), dim3(32, 8)>>>(W);
    gemm_hybrid<<<2048, 256, SMEM_DYN>>>(x, W);
    scan_kernel<<<(B * H) / 256, 256>>>(bias, out);
}

// round 10
// speedup vs baseline: 1.6936x; 1.0370x over previous
#include <cuda_runtime.h>
#include <cuda_fp16.h>
#include <cstdint>

// ---------------------------------------------------------------------------
// Problem constants
// ---------------------------------------------------------------------------
constexpr int B = 64;
constexpr int I = 512;
constexpr int T = 512;
constexpr int H = 1024;
constexpr float DECAY = 0.8f;

// ---------------------------------------------------------------------------
// Device scratch
// ---------------------------------------------------------------------------
__device__ __half g_Ax[(size_t)B * T * I];          // fp16(x^T)          (b,t,i)
__device__ __half g_Wh[(size_t)H * I];              // fp16 hi of W^T-0.5 (h,i)
__device__ __half g_Wl[(size_t)H * I];              // fp16 lo of W^T-0.5
__device__ float  g_part[(size_t)B * 16 * T];       // partial rowsums
__device__ float  g_csum[(size_t)B * T];            // 0.5 * sum_i x[b,i,t]
__device__ float  g_proj[(size_t)T * B * H];        // proj (t, b, h)

// ---------------------------------------------------------------------------
// PTX helpers
// ---------------------------------------------------------------------------
__device__ __forceinline__ uint32_t s2u(const void* p) {
    uint32_t a;
    asm("{ .reg .u64 t; cvta.to.shared.u64 t, %1; cvt.u32.u64 %0, t; }"
        : "=r"(a) : "l"(p));
    return a;
}
__device__ __forceinline__ void cp16(uint32_t dst, const void* src) {
    asm volatile("cp.async.cg.shared.global [%0], [%1], 16;" :: "r"(dst), "l"(src));
}
__device__ __forceinline__ void cp_commit() {
    asm volatile("cp.async.commit_group;" ::: "memory");
}
template <int N>
__device__ __forceinline__ void cp_wait() {
    asm volatile("cp.async.wait_group %0;" :: "n"(N) : "memory");
}
__device__ __forceinline__ void ldm_x4(uint32_t& r0, uint32_t& r1, uint32_t& r2,
                                       uint32_t& r3, uint32_t addr) {
    asm volatile("ldmatrix.sync.aligned.m8n8.x4.shared.b16 {%0,%1,%2,%3}, [%4];"
                 : "=r"(r0), "=r"(r1), "=r"(r2), "=r"(r3) : "r"(addr));
}
__device__ __forceinline__ void mma16816(float* d, const uint32_t* a,
                                         uint32_t b0, uint32_t b1) {
    asm volatile(
        "mma.sync.aligned.m16n8k16.row.col.f32.f16.f16.f32 "
        "{%0,%1,%2,%3}, {%4,%5,%6,%7}, {%8,%9}, {%0,%1,%2,%3};"
        : "+f"(d[0]), "+f"(d[1]), "+f"(d[2]), "+f"(d[3])
        : "r"(a[0]), "r"(a[1]), "r"(a[2]), "r"(a[3]), "r"(b0), "r"(b1));
}
// packed fp32 pair ops
__device__ __forceinline__ void fma2(uint64_t& d, uint64_t a, uint64_t b) {
    asm("fma.rn.f32x2 %0, %1, %2, %0;" : "+l"(d) : "l"(a), "l"(b));
}
__device__ __forceinline__ uint64_t pack2(float v) {
    uint64_t r; asm("mov.b64 %0, {%1, %1};" : "=l"(r) : "f"(v)); return r;
}
__device__ __forceinline__ void unpack2(uint64_t p, float& lo, float& hi) {
    asm("mov.b64 {%0, %1}, %2;" : "=f"(lo), "=f"(hi) : "l"(p));
}

// ---------------------------------------------------------------------------
// Kernel 1: transpose x (B,I,T) fp32 -> (B,T,I) fp16, + partial rowsums
// ---------------------------------------------------------------------------
__global__ __launch_bounds__(256)
void conv_x(const float* __restrict__ x) {
    __shared__ float tile[32][33];
    __shared__ float psum[8][32];
    const int b  = blockIdx.z;
    const int t0 = blockIdx.x * 32;
    const int i0 = blockIdx.y * 32;
    const int tx = threadIdx.x;
    const int ty = threadIdx.y;

    const float* src = x + ((size_t)b * I + i0) * T + t0;
#pragma unroll
    for (int k = 0; k < 4; ++k)
        tile[ty + k * 8][tx] = src[(size_t)(ty + k * 8) * T + tx];
    __syncthreads();

    __half* dh = g_Ax + ((size_t)b * T + t0) * I + i0;
#pragma unroll
    for (int k = 0; k < 4; ++k) {
        const int r = ty + k * 8;
        dh[(size_t)r * I + tx] = __float2half(tile[tx][r]);
    }

    float s = 0.0f;
#pragma unroll
    for (int k = 0; k < 4; ++k) s += tile[ty * 4 + k][tx];
    psum[ty][tx] = s;
    __syncthreads();
    if (ty == 0) {
        float tot = 0.0f;
#pragma unroll
        for (int j = 0; j < 8; ++j) tot += psum[j][tx];
        g_part[((size_t)b * 16 + blockIdx.y) * T + t0 + tx] = tot;
    }
}

__global__ __launch_bounds__(256)
void reduce_csum() {
    const int gid = blockIdx.x * blockDim.x + threadIdx.x;
    const int b = gid >> 9;
    const int t = gid & (T - 1);
    float s = 0.0f;
#pragma unroll
    for (int it = 0; it < 16; ++it)
        s += g_part[((size_t)b * 16 + it) * T + t];
    g_csum[(size_t)b * T + t] = 0.5f * s;
}

// ---------------------------------------------------------------------------
// Kernel 2: transpose W (I,H) fp32 -> (H,I), W-0.5 split into fp16 hi/lo
// ---------------------------------------------------------------------------
__global__ __launch_bounds__(256)
void conv_w(const float* __restrict__ W) {
    __shared__ float tile[32][33];
    const int h0 = blockIdx.x * 32;
    const int i0 = blockIdx.y * 32;
    const int tx = threadIdx.x;
    const int ty = threadIdx.y;

    const float* src = W + ((size_t)i0) * H + h0;
#pragma unroll
    for (int k = 0; k < 4; ++k)
        tile[ty + k * 8][tx] = src[(size_t)(ty + k * 8) * H + tx];
    __syncthreads();

    __half* dh = g_Wh + ((size_t)h0) * I + i0;
    __half* dl = g_Wl + ((size_t)h0) * I + i0;
#pragma unroll
    for (int k = 0; k < 4; ++k) {
        const int r = ty + k * 8;
        const float v = tile[tx][r] - 0.5f;
        const __half hi = __float2half(v);
        const __half lo = __float2half(v - __half2float(hi));
        dh[(size_t)r * I + tx] = hi;
        dl[(size_t)r * I + tx] = lo;
    }
}

// ---------------------------------------------------------------------------
// Kernel 3: hybrid GEMM, 2/8 fp32 : 6/8 mma(2-product).
// Both paths now use cp.async pipelines (fp32 staging LDG/STS removed to cut
// its issue-slot + crossbar share, which was throttling it to 42% in hybrid).
// ---------------------------------------------------------------------------
constexpr int BM = 128, BN = 128;

// mma-path config
constexpr int KC = 32;
constexpr int STAGES = 4;
constexpr int NSTG = 2 * (I / KC);              // 32
constexpr int ROWE = KC + 8;
constexpr int ROWB = ROWE * 2;                  // 80 bytes
constexpr int TILE_BYTES  = BM * ROWB;          // 10240
constexpr int STAGE_BYTES = 2 * TILE_BYTES;     // 20480
constexpr int SMEM_DYN = STAGES * STAGE_BYTES;  // 81920

// fp32-path config: 4-stage cp.async, FK=16 k-tile, stage = 8KB A + 8KB B
constexpr int FK = 16;
constexpr int FTM = 8, FTN = 8;
constexpr int F_TILE  = FK * BM * 4;            // 8192
constexpr int F_STAGE = 2 * F_TILE;             // 16384 (A then B)

__global__ __launch_bounds__(256, 2)
void gemm_hybrid(const float* __restrict__ x, const float* __restrict__ W) {
    extern __shared__ __align__(128) char smem[];
    const int tid = threadIdx.x;
    const int bid = blockIdx.x;
    const int sub = bid & 7;
    const bool is_fp32 = sub < 2;

    if (is_fp32) {
        // ---------------- fp32 SGEMM (f32x2 + cp.async), h0 in [0,256) -----
        const int q  = (bid >> 3) * 2 + sub;            // 0..511
        const int hb = q & 1;
        const int r  = q >> 1;
        const int tb = r & 3;
        const int b  = r >> 2;
        const int t0 = tb * BM;
        const int h0 = hb * BN;

        const uint32_t sb = s2u(smem);
        const float* Ab = x + (size_t)b * I * T + t0;   // (i,t): Ab[i*T+t]
        const float* Bb = W + h0;                       // (i,n): Bb[i*H+n]

        const int rf = tid >> 5;        // 0..7  (k-row; +8 for second chunk)
        const int cf = tid & 31;        // 16B column (0..31)

        auto load_stage = [&](int kt) {
            const uint32_t sA = sb + (kt & 3) * F_STAGE;
            const uint32_t sB = sA + F_TILE;
            const float* Ap = Ab + (size_t)kt * FK * T;
            const float* Bp = Bb + (size_t)kt * FK * H;
            cp16(sA + rf * 512 + cf * 16,       Ap + (size_t)rf * T + cf * 4);
            cp16(sA + (rf + 8) * 512 + cf * 16, Ap + (size_t)(rf + 8) * T + cf * 4);
            cp16(sB + rf * 512 + cf * 16,       Bp + (size_t)rf * H + cf * 4);
            cp16(sB + (rf + 8) * 512 + cf * 16, Bp + (size_t)(rf + 8) * H + cf * 4);
        };

        load_stage(0); cp_commit();
        load_stage(1); cp_commit();
        load_stage(2); cp_commit();

        const int tx  = tid & 15;
        const int ty  = tid >> 4;
        const int tm0 = ty * FTM;
        const int tn0 = tx * FTN;

        uint64_t acc2[FTM][FTN / 2];
#pragma unroll
        for (int i = 0; i < FTM; ++i)
#pragma unroll
            for (int j = 0; j < FTN / 2; ++j) acc2[i][j] = 0ull;

        constexpr int KT = I / FK;                      // 32
        for (int kt = 0; kt < KT; ++kt) {
            cp_wait<2>();
            __syncthreads();
            if (kt + 3 < KT) load_stage(kt + 3);
            cp_commit();

            const float* As = (const float*)(smem + (kt & 3) * F_STAGE);
            const float* Bs = (const float*)(smem + (kt & 3) * F_STAGE + F_TILE);
#pragma unroll
            for (int kk = 0; kk < FK; ++kk) {
                float a[FTM];
                uint64_t bb2[FTN / 2];
                *(float4*)&a[0] = *(const float4*)&As[kk * BM + tm0];
                *(float4*)&a[4] = *(const float4*)&As[kk * BM + tm0 + 4];
                *(ulonglong2*)&bb2[0] = *(const ulonglong2*)&Bs[kk * BN + tn0];
                *(ulonglong2*)&bb2[2] = *(const ulonglong2*)&Bs[kk * BN + tn0 + 4];
#pragma unroll
                for (int i = 0; i < FTM; ++i) {
                    const uint64_t aa = pack2(a[i]);
#pragma unroll
                    for (int j = 0; j < FTN / 2; ++j)
                        fma2(acc2[i][j], aa, bb2[j]);
                }
            }
        }

#pragma unroll
        for (int i = 0; i < FTM; ++i) {
            const int t = t0 + tm0 + i;
            float v[FTN];
#pragma unroll
            for (int j = 0; j < FTN / 2; ++j)
                unpack2(acc2[i][j], v[2 * j], v[2 * j + 1]);
            float* out = g_proj + ((size_t)t * B + b) * H + h0 + tn0;
            *(float4*)(out)     = make_float4(v[0], v[1], v[2], v[3]);
            *(float4*)(out + 4) = make_float4(v[4], v[5], v[6], v[7]);
        }
    } else {
        // -------- fp16 2-product MMA, h0 in [256,1024) --------
        const int q  = (bid >> 3) * 6 + (sub - 2);      // 0..1535
        const int hb = q % 6;
        const int r  = q / 6;
        const int tb = r & 3;
        const int b  = r >> 2;
        const int t0 = tb * BM;
        const int h0 = 256 + hb * BN;

        const uint32_t sb = s2u(smem);
        const int warp = tid >> 5;
        const int lane = tid & 31;
        const int wm = warp & 1;
        const int wn = warp >> 1;

        const int r0 = tid >> 1;
        const int c0 = (tid * 2) & 3;
        const int c1 = c0 + 1;

        const __half* Ab = g_Ax + ((size_t)(b * T + t0)) * I;
        const __half* Bh = g_Wh + ((size_t)h0) * I;
        const __half* Bl = g_Wl + ((size_t)h0) * I;

        auto load_stage = [&](int s) {
            const int ph = s >> 4;                      // 0: Whi, 1: Wlo
            const int kc = s & 15;
            const size_t i0 = (size_t)kc * KC;
            const __half* Ap = Ab + i0;
            const __half* Bp = (ph ? Bl : Bh) + i0;
            const uint32_t sA = sb + (s % STAGES) * STAGE_BYTES;
            const uint32_t sB = sA + TILE_BYTES;
            cp16(sA + r0 * ROWB + c0 * 16, Ap + (size_t)r0 * I + c0 * 8);
            cp16(sA + r0 * ROWB + c1 * 16, Ap + (size_t)r0 * I + c1 * 8);
            cp16(sB + r0 * ROWB + c0 * 16, Bp + (size_t)r0 * I + c0 * 8);
            cp16(sB + r0 * ROWB + c1 * 16, Bp + (size_t)r0 * I + c1 * 8);
        };

        load_stage(0); cp_commit();
        load_stage(1); cp_commit();
        load_stage(2); cp_commit();

        float acc[4][4][4];
#pragma unroll
        for (int mt = 0; mt < 4; ++mt)
#pragma unroll
            for (int nj = 0; nj < 4; ++nj)
#pragma unroll
                for (int rr = 0; rr < 4; ++rr) acc[mt][nj][rr] = 0.0f;

        const int a_row = (lane & 15);
        const int a_kh  = (lane >> 4) * 8;
        const int b_row = (lane & 7) + ((lane >> 4) << 3);
        const int b_kh  = ((lane >> 3) & 1) * 8;

        for (int s = 0; s < NSTG; ++s) {
            cp_wait<STAGES - 2>();
            __syncthreads();
            if (s + STAGES - 1 < NSTG) load_stage(s + STAGES - 1);
            cp_commit();

            const uint32_t sA = sb + (s % STAGES) * STAGE_BYTES;
            const uint32_t sB = sA + TILE_BYTES;

#pragma unroll
            for (int kk = 0; kk < KC; kk += 16) {
                uint32_t a[4][4], bb[2][4];
#pragma unroll
                for (int mt = 0; mt < 4; ++mt) {
                    const int m = wm * 64 + mt * 16 + a_row;
                    ldm_x4(a[mt][0], a[mt][1], a[mt][2], a[mt][3],
                           sA + m * ROWB + (kk + a_kh) * 2);
                }
#pragma unroll
                for (int nt = 0; nt < 2; ++nt) {
                    const int n = wn * 32 + nt * 16 + b_row;
                    ldm_x4(bb[nt][0], bb[nt][1], bb[nt][2], bb[nt][3],
                           sB + n * ROWB + (kk + b_kh) * 2);
                }
#pragma unroll
                for (int mt = 0; mt < 4; ++mt)
#pragma unroll
                    for (int nj = 0; nj < 4; ++nj) {
                        const int nt = nj >> 1;
                        const int hh = (nj & 1) * 2;
                        mma16816(acc[mt][nj], a[mt], bb[nt][hh], bb[nt][hh + 1]);
                    }
            }
            __syncthreads();
        }

        // Epilogue: add 0.5*rowsum(x) (exact fp32), store proj
#pragma unroll
        for (int mt = 0; mt < 4; ++mt) {
            const int tg = t0 + wm * 64 + mt * 16 + (lane >> 2);
            const float cc0 = g_csum[(size_t)b * T + tg];
            const float cc1 = g_csum[(size_t)b * T + tg + 8];
#pragma unroll
            for (int nj = 0; nj < 4; ++nj) {
                const int h = h0 + wn * 32 + nj * 8 + (lane & 3) * 2;
                float* o0 = g_proj + ((size_t)tg * B + b) * H + h;
                float* o1 = g_proj + ((size_t)(tg + 8) * B + b) * H + h;
                *(float2*)o0 = make_float2(acc[mt][nj][0] + cc0, acc[mt][nj][1] + cc0);
                *(float2*)o1 = make_float2(acc[mt][nj][2] + cc1, acc[mt][nj][3] + cc1);
            }
        }
    }
}

// ---------------------------------------------------------------------------
// Kernel 4: sequential recurrence, prefetch depth 2 (compute/batch < DRAM
// latency, so depth-1 left warps latency-stalled at 47% DRAM).
// ---------------------------------------------------------------------------
__global__ __launch_bounds__(256)
void scan_kernel(const float* __restrict__ bias, float* __restrict__ out) {
    const int gid = blockIdx.x * blockDim.x + threadIdx.x;
    const int b = gid >> 10;
    const int h = gid & (H - 1);

    const float bv = __ldg(bias + h);
    const float* p = g_proj + (size_t)b * H + h;
    constexpr int STRIDE = B * H;
    constexpr int CH = 16;

    float hc = 0.0f, y = 0.0f;
    float b0[CH], b1[CH];
#pragma unroll
    for (int j = 0; j < CH; ++j) b0[j] = p[(size_t)j * STRIDE];
#pragma unroll
    for (int j = 0; j < CH; ++j) b1[j] = p[(size_t)(CH + j) * STRIDE];

    for (int tt = 0; tt < T; tt += CH) {
        float b2[CH];
        if (tt + 2 * CH < T) {
            const float* pn = p + (size_t)(tt + 2 * CH) * STRIDE;
#pragma unroll
            for (int j = 0; j < CH; ++j) b2[j] = pn[(size_t)j * STRIDE];
        } else {
#pragma unroll
            for (int j = 0; j < CH; ++j) b2[j] = 0.0f;
        }
#pragma unroll
        for (int j = 0; j < CH; ++j) {
            hc = fmaxf(b0[j] + DECAY * hc * (1.0f - y), 0.0f);
            const float z = hc + bv;
            y = (z > 1.0f) ? z : 0.0f;
        }
#pragma unroll
        for (int j = 0; j < CH; ++j) b0[j] = b1[j];
#pragma unroll
        for (int j = 0; j < CH; ++j) b1[j] = b2[j];
    }
    out[gid] = y;
}

// ---------------------------------------------------------------------------
extern "C" void kernel_launch(void* const* d_in, const int* in_sizes, int n_in,
                              void* d_out, int out_size) {
    const float* x    = (const float*)d_in[0];  // (B, I, T)
    const float* W    = (const float*)d_in[1];  // (I, H)
    const float* bias = (const float*)d_in[2];  // (1, H)
    float* out        = (float*)d_out;          // (B, H)

    cudaFuncSetAttribute(gemm_hybrid, cudaFuncAttributeMaxDynamicSharedMemorySize,
                         SMEM_DYN);

    conv_x<<<dim3(T / 32, I / 32, B), dim3(32, 8)>>>(x);
    reduce_csum<<<(B * T) / 256, 256>>>();
    conv_w<<<dim3(H / 32, I / 32), dim3(32, 8)>>>(W);
    gemm_hybrid<<<2048, 256, SMEM_DYN>>>(x, W);
    scan_kernel<<<(B * H) / 256, 256>>>(bias, out);
}

// round 11
// speedup vs baseline: 1.8183x; 1.0736x over previous
#include <cuda_runtime.h>
#include <cuda_fp16.h>
#include <cstdint>

// ---------------------------------------------------------------------------
// Problem constants
// ---------------------------------------------------------------------------
constexpr int B = 64;
constexpr int I = 512;
constexpr int T = 512;
constexpr int H = 1024;
constexpr float DECAY = 0.8f;

// ---------------------------------------------------------------------------
// Device scratch
// ---------------------------------------------------------------------------
__device__ __half g_Ax[(size_t)B * T * I];          // fp16(x^T)          (b,t,i)
__device__ __half g_Wh[(size_t)H * I];              // fp16 hi of W^T-0.5 (h,i)
__device__ __half g_Wl[(size_t)H * I];              // fp16 lo of W^T-0.5
__device__ float  g_part[(size_t)B * 16 * T];       // partial rowsums
__device__ float  g_csum[(size_t)B * T];            // 0.5 * sum_i x[b,i,t]
__device__ float  g_proj[(size_t)T * B * H];        // proj (t, b, h)

// ---------------------------------------------------------------------------
// PTX helpers
// ---------------------------------------------------------------------------
__device__ __forceinline__ uint32_t s2u(const void* p) {
    uint32_t a;
    asm("{ .reg .u64 t; cvta.to.shared.u64 t, %1; cvt.u32.u64 %0, t; }"
        : "=r"(a) : "l"(p));
    return a;
}
__device__ __forceinline__ void cp16(uint32_t dst, const void* src) {
    asm volatile("cp.async.cg.shared.global [%0], [%1], 16;" :: "r"(dst), "l"(src));
}
__device__ __forceinline__ void cp_commit() {
    asm volatile("cp.async.commit_group;" ::: "memory");
}
template <int N>
__device__ __forceinline__ void cp_wait() {
    asm volatile("cp.async.wait_group %0;" :: "n"(N) : "memory");
}
__device__ __forceinline__ void ldm_x4(uint32_t& r0, uint32_t& r1, uint32_t& r2,
                                       uint32_t& r3, uint32_t addr) {
    asm volatile("ldmatrix.sync.aligned.m8n8.x4.shared.b16 {%0,%1,%2,%3}, [%4];"
                 : "=r"(r0), "=r"(r1), "=r"(r2), "=r"(r3) : "r"(addr));
}
__device__ __forceinline__ void mma16816(float* d, const uint32_t* a,
                                         uint32_t b0, uint32_t b1) {
    asm volatile(
        "mma.sync.aligned.m16n8k16.row.col.f32.f16.f16.f32 "
        "{%0,%1,%2,%3}, {%4,%5,%6,%7}, {%8,%9}, {%0,%1,%2,%3};"
        : "+f"(d[0]), "+f"(d[1]), "+f"(d[2]), "+f"(d[3])
        : "r"(a[0]), "r"(a[1]), "r"(a[2]), "r"(a[3]), "r"(b0), "r"(b1));
}
// packed fp32 pair ops
__device__ __forceinline__ void fma2(uint64_t& d, uint64_t a, uint64_t b) {
    asm("fma.rn.f32x2 %0, %1, %2, %0;" : "+l"(d) : "l"(a), "l"(b));
}
__device__ __forceinline__ uint64_t pack2(float v) {
    uint64_t r; asm("mov.b64 %0, {%1, %1};" : "=l"(r) : "f"(v)); return r;
}
__device__ __forceinline__ void unpack2(uint64_t p, float& lo, float& hi) {
    asm("mov.b64 {%0, %1}, %2;" : "=f"(lo), "=f"(hi) : "l"(p));
}

// ---------------------------------------------------------------------------
// Kernel 1: transpose x (B,I,T) fp32 -> (B,T,I) fp16, + partial rowsums
// ---------------------------------------------------------------------------
__global__ __launch_bounds__(256)
void conv_x(const float* __restrict__ x) {
    __shared__ float tile[32][33];
    __shared__ float psum[8][32];
    const int b  = blockIdx.z;
    const int t0 = blockIdx.x * 32;
    const int i0 = blockIdx.y * 32;
    const int tx = threadIdx.x;
    const int ty = threadIdx.y;

    const float* src = x + ((size_t)b * I + i0) * T + t0;
#pragma unroll
    for (int k = 0; k < 4; ++k)
        tile[ty + k * 8][tx] = src[(size_t)(ty + k * 8) * T + tx];
    __syncthreads();

    __half* dh = g_Ax + ((size_t)b * T + t0) * I + i0;
#pragma unroll
    for (int k = 0; k < 4; ++k) {
        const int r = ty + k * 8;
        dh[(size_t)r * I + tx] = __float2half(tile[tx][r]);
    }

    float s = 0.0f;
#pragma unroll
    for (int k = 0; k < 4; ++k) s += tile[ty * 4 + k][tx];
    psum[ty][tx] = s;
    __syncthreads();
    if (ty == 0) {
        float tot = 0.0f;
#pragma unroll
        for (int j = 0; j < 8; ++j) tot += psum[j][tx];
        g_part[((size_t)b * 16 + blockIdx.y) * T + t0 + tx] = tot;
    }
}

__global__ __launch_bounds__(256)
void reduce_csum() {
    const int gid = blockIdx.x * blockDim.x + threadIdx.x;
    const int b = gid >> 9;
    const int t = gid & (T - 1);
    float s = 0.0f;
#pragma unroll
    for (int it = 0; it < 16; ++it)
        s += g_part[((size_t)b * 16 + it) * T + t];
    g_csum[(size_t)b * T + t] = 0.5f * s;
}

// ---------------------------------------------------------------------------
// Kernel 2: transpose W (I,H) fp32 -> (H,I), W-0.5 split into fp16 hi/lo
// ---------------------------------------------------------------------------
__global__ __launch_bounds__(256)
void conv_w(const float* __restrict__ W) {
    __shared__ float tile[32][33];
    const int h0 = blockIdx.x * 32;
    const int i0 = blockIdx.y * 32;
    const int tx = threadIdx.x;
    const int ty = threadIdx.y;

    const float* src = W + ((size_t)i0) * H + h0;
#pragma unroll
    for (int k = 0; k < 4; ++k)
        tile[ty + k * 8][tx] = src[(size_t)(ty + k * 8) * H + tx];
    __syncthreads();

    __half* dh = g_Wh + ((size_t)h0) * I + i0;
    __half* dl = g_Wl + ((size_t)h0) * I + i0;
#pragma unroll
    for (int k = 0; k < 4; ++k) {
        const int r = ty + k * 8;
        const float v = tile[tx][r] - 0.5f;
        const __half hi = __float2half(v);
        const __half lo = __float2half(v - __half2float(hi));
        dh[(size_t)r * I + tx] = hi;
        dl[(size_t)r * I + tx] = lo;
    }
}

// ---------------------------------------------------------------------------
// Kernel 3: hybrid GEMM, 2/8 fp32 : 6/8 mma.
// mma path restructured: 16 stages of (A, Bhi, Blo) — A loaded ONCE and its
// ldmatrix frags reused for both W products (same accumulator). This cuts
// cp.async traffic 25%, ldmatrix ops 33%, and barriers 75% vs round 10.
// ---------------------------------------------------------------------------
constexpr int BM = 128, BN = 128;

// mma-path config: 16 kc chunks, 3-stage (A,Bh,Bl) pipeline
constexpr int KC = 32;
constexpr int STAGES = 3;
constexpr int NSTG = I / KC;                    // 16
constexpr int ROWE = KC + 8;
constexpr int ROWB = ROWE * 2;                  // 80 bytes
constexpr int TILE_BYTES  = BM * ROWB;          // 10240
constexpr int STAGE_BYTES = 3 * TILE_BYTES;     // 30720 (A, Bh, Bl)
constexpr int SMEM_DYN = STAGES * STAGE_BYTES;  // 92160

// fp32-path config: 4-stage cp.async, FK=16 k-tile
constexpr int FK = 16;
constexpr int FTM = 8, FTN = 8;
constexpr int F_TILE  = FK * BM * 4;            // 8192
constexpr int F_STAGE = 2 * F_TILE;             // 16384

__global__ __launch_bounds__(256, 2)
void gemm_hybrid(const float* __restrict__ x, const float* __restrict__ W) {
    extern __shared__ __align__(128) char smem[];
    const int tid = threadIdx.x;
    const int bid = blockIdx.x;
    const int sub = bid & 7;
    const bool is_fp32 = sub < 2;

    if (is_fp32) {
        // ---------------- fp32 SGEMM (f32x2 + cp.async), h0 in [0,256) -----
        const int q  = (bid >> 3) * 2 + sub;            // 0..511
        const int hb = q & 1;
        const int r  = q >> 1;
        const int tb = r & 3;
        const int b  = r >> 2;
        const int t0 = tb * BM;
        const int h0 = hb * BN;

        const uint32_t sb = s2u(smem);
        const float* Ab = x + (size_t)b * I * T + t0;
        const float* Bb = W + h0;

        const int rf = tid >> 5;
        const int cf = tid & 31;

        auto load_stage = [&](int kt) {
            const uint32_t sA = sb + (kt & 3) * F_STAGE;
            const uint32_t sB = sA + F_TILE;
            const float* Ap = Ab + (size_t)kt * FK * T;
            const float* Bp = Bb + (size_t)kt * FK * H;
            cp16(sA + rf * 512 + cf * 16,       Ap + (size_t)rf * T + cf * 4);
            cp16(sA + (rf + 8) * 512 + cf * 16, Ap + (size_t)(rf + 8) * T + cf * 4);
            cp16(sB + rf * 512 + cf * 16,       Bp + (size_t)rf * H + cf * 4);
            cp16(sB + (rf + 8) * 512 + cf * 16, Bp + (size_t)(rf + 8) * H + cf * 4);
        };

        load_stage(0); cp_commit();
        load_stage(1); cp_commit();
        load_stage(2); cp_commit();

        const int tx  = tid & 15;
        const int ty  = tid >> 4;
        const int tm0 = ty * FTM;
        const int tn0 = tx * FTN;

        uint64_t acc2[FTM][FTN / 2];
#pragma unroll
        for (int i = 0; i < FTM; ++i)
#pragma unroll
            for (int j = 0; j < FTN / 2; ++j) acc2[i][j] = 0ull;

        constexpr int KT = I / FK;                      // 32
        for (int kt = 0; kt < KT; ++kt) {
            cp_wait<2>();
            __syncthreads();
            if (kt + 3 < KT) load_stage(kt + 3);
            cp_commit();

            const float* As = (const float*)(smem + (kt & 3) * F_STAGE);
            const float* Bs = (const float*)(smem + (kt & 3) * F_STAGE + F_TILE);
#pragma unroll
            for (int kk = 0; kk < FK; ++kk) {
                float a[FTM];
                uint64_t bb2[FTN / 2];
                *(float4*)&a[0] = *(const float4*)&As[kk * BM + tm0];
                *(float4*)&a[4] = *(const float4*)&As[kk * BM + tm0 + 4];
                *(ulonglong2*)&bb2[0] = *(const ulonglong2*)&Bs[kk * BN + tn0];
                *(ulonglong2*)&bb2[2] = *(const ulonglong2*)&Bs[kk * BN + tn0 + 4];
#pragma unroll
                for (int i = 0; i < FTM; ++i) {
                    const uint64_t aa = pack2(a[i]);
#pragma unroll
                    for (int j = 0; j < FTN / 2; ++j)
                        fma2(acc2[i][j], aa, bb2[j]);
                }
            }
        }

#pragma unroll
        for (int i = 0; i < FTM; ++i) {
            const int t = t0 + tm0 + i;
            float v[FTN];
#pragma unroll
            for (int j = 0; j < FTN / 2; ++j)
                unpack2(acc2[i][j], v[2 * j], v[2 * j + 1]);
            float* out = g_proj + ((size_t)t * B + b) * H + h0 + tn0;
            *(float4*)(out)     = make_float4(v[0], v[1], v[2], v[3]);
            *(float4*)(out + 4) = make_float4(v[4], v[5], v[6], v[7]);
        }
    } else {
        // -------- fp16 2-product MMA (A-dedup), h0 in [256,1024) --------
        const int q  = (bid >> 3) * 6 + (sub - 2);      // 0..1535
        const int hb = q % 6;
        const int r  = q / 6;
        const int tb = r & 3;
        const int b  = r >> 2;
        const int t0 = tb * BM;
        const int h0 = 256 + hb * BN;

        const uint32_t sb = s2u(smem);
        const int warp = tid >> 5;
        const int lane = tid & 31;
        const int wm = warp & 1;
        const int wn = warp >> 1;

        const int r0 = tid >> 1;
        const int c0 = (tid * 2) & 3;
        const int c1 = c0 + 1;

        const __half* Abase = g_Ax + ((size_t)(b * T + t0)) * I;
        const __half* Bhb = g_Wh + ((size_t)h0) * I;
        const __half* Blb = g_Wl + ((size_t)h0) * I;

        auto load_stage = [&](int kc) {
            const size_t i0 = (size_t)kc * KC;
            const uint32_t sA  = sb + (kc % STAGES) * STAGE_BYTES;
            const uint32_t sBh = sA + TILE_BYTES;
            const uint32_t sBl = sBh + TILE_BYTES;
            const __half* Ap  = Abase + i0;
            const __half* Bhp = Bhb + i0;
            const __half* Blp = Blb + i0;
            cp16(sA  + r0 * ROWB + c0 * 16, Ap  + (size_t)r0 * I + c0 * 8);
            cp16(sA  + r0 * ROWB + c1 * 16, Ap  + (size_t)r0 * I + c1 * 8);
            cp16(sBh + r0 * ROWB + c0 * 16, Bhp + (size_t)r0 * I + c0 * 8);
            cp16(sBh + r0 * ROWB + c1 * 16, Bhp + (size_t)r0 * I + c1 * 8);
            cp16(sBl + r0 * ROWB + c0 * 16, Blp + (size_t)r0 * I + c0 * 8);
            cp16(sBl + r0 * ROWB + c1 * 16, Blp + (size_t)r0 * I + c1 * 8);
        };

        load_stage(0); cp_commit();
        load_stage(1); cp_commit();

        float acc[4][4][4];
#pragma unroll
        for (int mt = 0; mt < 4; ++mt)
#pragma unroll
            for (int nj = 0; nj < 4; ++nj)
#pragma unroll
                for (int rr = 0; rr < 4; ++rr) acc[mt][nj][rr] = 0.0f;

        const int a_row = (lane & 15);
        const int a_kh  = (lane >> 4) * 8;
        const int b_row = (lane & 7) + ((lane >> 4) << 3);
        const int b_kh  = ((lane >> 3) & 1) * 8;

        for (int s = 0; s < NSTG; ++s) {
            cp_wait<STAGES - 2>();
            __syncthreads();          // single barrier per stage (see header)
            if (s + STAGES - 1 < NSTG) load_stage(s + STAGES - 1);
            cp_commit();

            const uint32_t sA  = sb + (s % STAGES) * STAGE_BYTES;
            const uint32_t sBh = sA + TILE_BYTES;
            const uint32_t sBl = sBh + TILE_BYTES;

#pragma unroll
            for (int kk = 0; kk < KC; kk += 16) {
                uint32_t a[4][4], bb[2][4];
                // A frags: loaded once, reused for both W products
#pragma unroll
                for (int mt = 0; mt < 4; ++mt) {
                    const int m = wm * 64 + mt * 16 + a_row;
                    ldm_x4(a[mt][0], a[mt][1], a[mt][2], a[mt][3],
                           sA + m * ROWB + (kk + a_kh) * 2);
                }
                // product 1: A * W_hi
#pragma unroll
                for (int nt = 0; nt < 2; ++nt) {
                    const int n = wn * 32 + nt * 16 + b_row;
                    ldm_x4(bb[nt][0], bb[nt][1], bb[nt][2], bb[nt][3],
                           sBh + n * ROWB + (kk + b_kh) * 2);
                }
#pragma unroll
                for (int mt = 0; mt < 4; ++mt)
#pragma unroll
                    for (int nj = 0; nj < 4; ++nj) {
                        const int nt = nj >> 1;
                        const int hh = (nj & 1) * 2;
                        mma16816(acc[mt][nj], a[mt], bb[nt][hh], bb[nt][hh + 1]);
                    }
                // product 2: A * W_lo (reuse bb registers)
#pragma unroll
                for (int nt = 0; nt < 2; ++nt) {
                    const int n = wn * 32 + nt * 16 + b_row;
                    ldm_x4(bb[nt][0], bb[nt][1], bb[nt][2], bb[nt][3],
                           sBl + n * ROWB + (kk + b_kh) * 2);
                }
#pragma unroll
                for (int mt = 0; mt < 4; ++mt)
#pragma unroll
                    for (int nj = 0; nj < 4; ++nj) {
                        const int nt = nj >> 1;
                        const int hh = (nj & 1) * 2;
                        mma16816(acc[mt][nj], a[mt], bb[nt][hh], bb[nt][hh + 1]);
                    }
            }
        }

        // Epilogue: add 0.5*rowsum(x) (exact fp32), store proj
#pragma unroll
        for (int mt = 0; mt < 4; ++mt) {
            const int tg = t0 + wm * 64 + mt * 16 + (lane >> 2);
            const float cc0 = g_csum[(size_t)b * T + tg];
            const float cc1 = g_csum[(size_t)b * T + tg + 8];
#pragma unroll
            for (int nj = 0; nj < 4; ++nj) {
                const int h = h0 + wn * 32 + nj * 8 + (lane & 3) * 2;
                float* o0 = g_proj + ((size_t)tg * B + b) * H + h;
                float* o1 = g_proj + ((size_t)(tg + 8) * B + b) * H + h;
                *(float2*)o0 = make_float2(acc[mt][nj][0] + cc0, acc[mt][nj][1] + cc0);
                *(float2*)o1 = make_float2(acc[mt][nj][2] + cc1, acc[mt][nj][3] + cc1);
            }
        }
    }
}

// ---------------------------------------------------------------------------
// Kernel 4: sequential recurrence, prefetch depth 2
// ---------------------------------------------------------------------------
__global__ __launch_bounds__(256)
void scan_kernel(const float* __restrict__ bias, float* __restrict__ out) {
    const int gid = blockIdx.x * blockDim.x + threadIdx.x;
    const int b = gid >> 10;
    const int h = gid & (H - 1);

    const float bv = __ldg(bias + h);
    const float* p = g_proj + (size_t)b * H + h;
    constexpr int STRIDE = B * H;
    constexpr int CH = 16;

    float hc = 0.0f, y = 0.0f;
    float b0[CH], b1[CH];
#pragma unroll
    for (int j = 0; j < CH; ++j) b0[j] = p[(size_t)j * STRIDE];
#pragma unroll
    for (int j = 0; j < CH; ++j) b1[j] = p[(size_t)(CH + j) * STRIDE];

    for (int tt = 0; tt < T; tt += CH) {
        float b2[CH];
        if (tt + 2 * CH < T) {
            const float* pn = p + (size_t)(tt + 2 * CH) * STRIDE;
#pragma unroll
            for (int j = 0; j < CH; ++j) b2[j] = pn[(size_t)j * STRIDE];
        } else {
#pragma unroll
            for (int j = 0; j < CH; ++j) b2[j] = 0.0f;
        }
#pragma unroll
        for (int j = 0; j < CH; ++j) {
            hc = fmaxf(b0[j] + DECAY * hc * (1.0f - y), 0.0f);
            const float z = hc + bv;
            y = (z > 1.0f) ? z : 0.0f;
        }
#pragma unroll
        for (int j = 0; j < CH; ++j) b0[j] = b1[j];
#pragma unroll
        for (int j = 0; j < CH; ++j) b1[j] = b2[j];
    }
    out[gid] = y;
}

// ---------------------------------------------------------------------------
extern "C" void kernel_launch(void* const* d_in, const int* in_sizes, int n_in,
                              void* d_out, int out_size) {
    const float* x    = (const float*)d_in[0];  // (B, I, T)
    const float* W    = (const float*)d_in[1];  // (I, H)
    const float* bias = (const float*)d_in[2];  // (1, H)
    float* out        = (float*)d_out;          // (B, H)

    cudaFuncSetAttribute(gemm_hybrid, cudaFuncAttributeMaxDynamicSharedMemorySize,
                         SMEM_DYN);

    conv_x<<<dim3(T / 32, I / 32, B), dim3(32, 8)>>>(x);
    reduce_csum<<<(B * T) / 256, 256>>>();
    conv_w<<<dim3(H / 32, I / 32), dim3(32, 8)>>>(W);
    gemm_hybrid<<<2048, 256, SMEM_DYN>>>(x, W);
    scan_kernel<<<(B * H) / 256, 256>>>(bias, out);
}

// round 12
// speedup vs baseline: 1.8613x; 1.0236x over previous
#include <cuda_runtime.h>
#include <cuda_fp16.h>
#include <cstdint>

// ---------------------------------------------------------------------------
// Problem constants
// ---------------------------------------------------------------------------
constexpr int B = 64;
constexpr int I = 512;
constexpr int T = 512;
constexpr int H = 1024;
constexpr float DECAY = 0.8f;

// ---------------------------------------------------------------------------
// Device scratch
// ---------------------------------------------------------------------------
__device__ __half g_Ax[(size_t)B * T * I];          // fp16(x^T)          (b,t,i)
__device__ __half g_Wh[(size_t)H * I];              // fp16 hi of W^T-0.5 (h,i)
__device__ __half g_Wl[(size_t)H * I];              // fp16 lo of W^T-0.5
__device__ float  g_part[(size_t)B * 8 * T];        // partial rowsums (64-i tiles)
__device__ float  g_csum[(size_t)B * T];            // 0.5 * sum_i x[b,i,t]
__device__ float  g_proj[(size_t)T * B * H];        // proj (t, b, h)
__device__ int    g_cnt[B];                         // per-b tile completion count

// ---------------------------------------------------------------------------
// PTX helpers
// ---------------------------------------------------------------------------
__device__ __forceinline__ uint32_t s2u(const void* p) {
    uint32_t a;
    asm("{ .reg .u64 t; cvta.to.shared.u64 t, %1; cvt.u32.u64 %0, t; }"
        : "=r"(a) : "l"(p));
    return a;
}
__device__ __forceinline__ void cp16(uint32_t dst, const void* src) {
    asm volatile("cp.async.cg.shared.global [%0], [%1], 16;" :: "r"(dst), "l"(src));
}
__device__ __forceinline__ void cp_commit() {
    asm volatile("cp.async.commit_group;" ::: "memory");
}
template <int N>
__device__ __forceinline__ void cp_wait() {
    asm volatile("cp.async.wait_group %0;" :: "n"(N) : "memory");
}
__device__ __forceinline__ void ldm_x4(uint32_t& r0, uint32_t& r1, uint32_t& r2,
                                       uint32_t& r3, uint32_t addr) {
    asm volatile("ldmatrix.sync.aligned.m8n8.x4.shared.b16 {%0,%1,%2,%3}, [%4];"
                 : "=r"(r0), "=r"(r1), "=r"(r2), "=r"(r3) : "r"(addr));
}
__device__ __forceinline__ void mma16816(float* d, const uint32_t* a,
                                         uint32_t b0, uint32_t b1) {
    asm volatile(
        "mma.sync.aligned.m16n8k16.row.col.f32.f16.f16.f32 "
        "{%0,%1,%2,%3}, {%4,%5,%6,%7}, {%8,%9}, {%0,%1,%2,%3};"
        : "+f"(d[0]), "+f"(d[1]), "+f"(d[2]), "+f"(d[3])
        : "r"(a[0]), "r"(a[1]), "r"(a[2]), "r"(a[3]), "r"(b0), "r"(b1));
}
// packed fp32 pair ops
__device__ __forceinline__ void fma2(uint64_t& d, uint64_t a, uint64_t b) {
    asm("fma.rn.f32x2 %0, %1, %2, %0;" : "+l"(d) : "l"(a), "l"(b));
}
__device__ __forceinline__ uint64_t pack2(float v) {
    uint64_t r; asm("mov.b64 %0, {%1, %1};" : "=l"(r) : "f"(v)); return r;
}
__device__ __forceinline__ void unpack2(uint64_t p, float& lo, float& hi) {
    asm("mov.b64 {%0, %1}, %2;" : "=f"(lo), "=f"(hi) : "l"(p));
}

// ---------------------------------------------------------------------------
// Kernel 1: transpose x (B,I,T) fp32 -> (B,T,I) fp16, + partial rowsums.
// 64-wide i tiles so g_Ax stores are 128B-per-row (full coalescing).
// ---------------------------------------------------------------------------
__global__ __launch_bounds__(256)
void conv_x(const float* __restrict__ x) {
    __shared__ float tile[64][33];
    __shared__ float psum[8][32];
    const int b  = blockIdx.z;
    const int t0 = blockIdx.x * 32;
    const int i0 = blockIdx.y * 64;
    const int tx = threadIdx.x;      // 0..31
    const int ty = threadIdx.y;      // 0..7

    const float* src = x + ((size_t)b * I + i0) * T + t0;
#pragma unroll
    for (int k = 0; k < 8; ++k)
        tile[ty + k * 8][tx] = src[(size_t)(ty + k * 8) * T + tx];
    __syncthreads();

    // Store: 32 t-rows x 64 i halves (128B/row). Thread -> (row, 8-i segment).
    {
        const int id  = ty * 32 + tx;
        const int r   = id >> 3;             // t row 0..31
        const int seg = id & 7;              // i segment 0..7
        float v[8];
#pragma unroll
        for (int j = 0; j < 8; ++j) v[j] = tile[seg * 8 + j][r];
        __half2 q0 = __floats2half2_rn(v[0], v[1]);
        __half2 q1 = __floats2half2_rn(v[2], v[3]);
        __half2 q2 = __floats2half2_rn(v[4], v[5]);
        __half2 q3 = __floats2half2_rn(v[6], v[7]);
        uint4 u;
        u.x = *reinterpret_cast<uint32_t*>(&q0);
        u.y = *reinterpret_cast<uint32_t*>(&q1);
        u.z = *reinterpret_cast<uint32_t*>(&q2);
        u.w = *reinterpret_cast<uint32_t*>(&q3);
        __half* dh = g_Ax + ((size_t)b * T + t0 + r) * I + i0 + seg * 8;
        *reinterpret_cast<uint4*>(dh) = u;
    }

    // Partial sums over this tile's 64 i's, per t
    float s = 0.0f;
#pragma unroll
    for (int k = 0; k < 8; ++k) s += tile[ty * 8 + k][tx];
    psum[ty][tx] = s;
    __syncthreads();
    if (ty == 0) {
        float tot = 0.0f;
#pragma unroll
        for (int j = 0; j < 8; ++j) tot += psum[j][tx];
        g_part[((size_t)b * 8 + blockIdx.y) * T + t0 + tx] = tot;
    }
}

// ---------------------------------------------------------------------------
// Kernel: reduce partials -> g_csum; also zero g_cnt for this iteration.
// ---------------------------------------------------------------------------
__global__ __launch_bounds__(256)
void reduce_csum() {
    const int gid = blockIdx.x * blockDim.x + threadIdx.x;
    if (gid < B) g_cnt[gid] = 0;
    const int b = gid >> 9;
    const int t = gid & (T - 1);
    float s = 0.0f;
#pragma unroll
    for (int it = 0; it < 8; ++it)
        s += g_part[((size_t)b * 8 + it) * T + t];
    g_csum[(size_t)b * T + t] = 0.5f * s;
}

// ---------------------------------------------------------------------------
// Kernel 2: transpose W (I,H) fp32 -> (H,I), W-0.5 split into fp16 hi/lo
// ---------------------------------------------------------------------------
__global__ __launch_bounds__(256)
void conv_w(const float* __restrict__ W) {
    __shared__ float tile[32][33];
    const int h0 = blockIdx.x * 32;
    const int i0 = blockIdx.y * 32;
    const int tx = threadIdx.x;
    const int ty = threadIdx.y;

    const float* src = W + ((size_t)i0) * H + h0;
#pragma unroll
    for (int k = 0; k < 4; ++k)
        tile[ty + k * 8][tx] = src[(size_t)(ty + k * 8) * H + tx];
    __syncthreads();

    __half* dh = g_Wh + ((size_t)h0) * I + i0;
    __half* dl = g_Wl + ((size_t)h0) * I + i0;
#pragma unroll
    for (int k = 0; k < 4; ++k) {
        const int r = ty + k * 8;
        const float v = tile[tx][r] - 0.5f;
        const __half hi = __float2half(v);
        const __half lo = __float2half(v - __half2float(hi));
        dh[(size_t)r * I + tx] = hi;
        dl[(size_t)r * I + tx] = lo;
    }
}

// ---------------------------------------------------------------------------
// Kernel 3: fused hybrid GEMM + scan.
//   bid in [0,2048):    GEMM tile CTAs (2/8 fp32, 6/8 mma 2-product).
//     Each tile CTA: epilogue stores -> fence -> atomicAdd(g_cnt[b]).
//   bid in [2048,2304): scan CTAs. Spin until g_cnt[b]==32 (all 32 tile CTAs
//     of batch b done), then run the recurrence. Scan bids come last -> they
//     run in the final wave, overlapping the compute-bound GEMM tail.
//   Both roles' b rises with bid; no deadlock (<=256 spinners < 296 slots).
// ---------------------------------------------------------------------------
constexpr int BM = 128, BN = 128;

// mma-path config: 16 kc chunks, 3-stage (A,Bh,Bl) pipeline
constexpr int KC = 32;
constexpr int STAGES = 3;
constexpr int NSTG = I / KC;                    // 16
constexpr int ROWE = KC + 8;
constexpr int ROWB = ROWE * 2;                  // 80 bytes
constexpr int TILE_BYTES  = BM * ROWB;          // 10240
constexpr int STAGE_BYTES = 3 * TILE_BYTES;     // 30720 (A, Bh, Bl)
constexpr int SMEM_DYN = STAGES * STAGE_BYTES;  // 92160

// fp32-path config: 4-stage cp.async, FK=16 k-tile
constexpr int FK = 16;
constexpr int FTM = 8, FTN = 8;
constexpr int F_TILE  = FK * BM * 4;            // 8192
constexpr int F_STAGE = 2 * F_TILE;             // 16384

__global__ __launch_bounds__(256, 2)
void gemm_hybrid(const float* __restrict__ x, const float* __restrict__ W,
                 const float* __restrict__ bias, float* __restrict__ out) {
    extern __shared__ __align__(128) char smem[];
    const int tid = threadIdx.x;
    const int bid = blockIdx.x;

    if (bid >= 2048) {
        // ================= scan role =================
        const int g    = bid - 2048;            // 0..255
        const int b    = g >> 2;
        const int part = g & 3;
        const int h    = part * 256 + tid;

        // Wait for all 32 tile CTAs of batch b
        if (tid == 0) {
            for (;;) {
                int v;
                asm volatile("ld.global.cg.s32 %0, [%1];" : "=r"(v)
                             : "l"(&g_cnt[b]));
                if (v >= 32) break;
                __nanosleep(512);
            }
        }
        __syncthreads();
        __threadfence();

        const float bv = __ldg(bias + h);
        const float* p = g_proj + (size_t)b * H + h;
        constexpr int STRIDE = B * H;
        constexpr int CH = 16;

        float hc = 0.0f, y = 0.0f;
        float b0[CH], b1[CH];
#pragma unroll
        for (int j = 0; j < CH; ++j) b0[j] = p[(size_t)j * STRIDE];
#pragma unroll
        for (int j = 0; j < CH; ++j) b1[j] = p[(size_t)(CH + j) * STRIDE];

        for (int tt = 0; tt < T; tt += CH) {
            float b2[CH];
            if (tt + 2 * CH < T) {
                const float* pn = p + (size_t)(tt + 2 * CH) * STRIDE;
#pragma unroll
                for (int j = 0; j < CH; ++j) b2[j] = pn[(size_t)j * STRIDE];
            } else {
#pragma unroll
                for (int j = 0; j < CH; ++j) b2[j] = 0.0f;
            }
#pragma unroll
            for (int j = 0; j < CH; ++j) {
                hc = fmaxf(b0[j] + DECAY * hc * (1.0f - y), 0.0f);
                const float z = hc + bv;
                y = (z > 1.0f) ? z : 0.0f;
            }
#pragma unroll
            for (int j = 0; j < CH; ++j) b0[j] = b1[j];
#pragma unroll
            for (int j = 0; j < CH; ++j) b1[j] = b2[j];
        }
        out[(size_t)b * H + h] = y;
        return;
    }

    const int sub = bid & 7;
    const bool is_fp32 = sub < 2;
    int b_done;                                 // batch of this tile CTA

    if (is_fp32) {
        // ---------------- fp32 SGEMM (f32x2 + cp.async), h0 in [0,256) -----
        const int q  = (bid >> 3) * 2 + sub;            // 0..511
        const int hb = q & 1;
        const int r  = q >> 1;
        const int tb = r & 3;
        const int b  = r >> 2;
        const int t0 = tb * BM;
        const int h0 = hb * BN;
        b_done = b;

        const uint32_t sb = s2u(smem);
        const float* Ab = x + (size_t)b * I * T + t0;
        const float* Bb = W + h0;

        const int rf = tid >> 5;
        const int cf = tid & 31;

        auto load_stage = [&](int kt) {
            const uint32_t sA = sb + (kt & 3) * F_STAGE;
            const uint32_t sB = sA + F_TILE;
            const float* Ap = Ab + (size_t)kt * FK * T;
            const float* Bp = Bb + (size_t)kt * FK * H;
            cp16(sA + rf * 512 + cf * 16,       Ap + (size_t)rf * T + cf * 4);
            cp16(sA + (rf + 8) * 512 + cf * 16, Ap + (size_t)(rf + 8) * T + cf * 4);
            cp16(sB + rf * 512 + cf * 16,       Bp + (size_t)rf * H + cf * 4);
            cp16(sB + (rf + 8) * 512 + cf * 16, Bp + (size_t)(rf + 8) * H + cf * 4);
        };

        load_stage(0); cp_commit();
        load_stage(1); cp_commit();
        load_stage(2); cp_commit();

        const int tx  = tid & 15;
        const int ty  = tid >> 4;
        const int tm0 = ty * FTM;
        const int tn0 = tx * FTN;

        uint64_t acc2[FTM][FTN / 2];
#pragma unroll
        for (int i = 0; i < FTM; ++i)
#pragma unroll
            for (int j = 0; j < FTN / 2; ++j) acc2[i][j] = 0ull;

        constexpr int KT = I / FK;                      // 32
        for (int kt = 0; kt < KT; ++kt) {
            cp_wait<2>();
            __syncthreads();
            if (kt + 3 < KT) load_stage(kt + 3);
            cp_commit();

            const float* As = (const float*)(smem + (kt & 3) * F_STAGE);
            const float* Bs = (const float*)(smem + (kt & 3) * F_STAGE + F_TILE);
#pragma unroll
            for (int kk = 0; kk < FK; ++kk) {
                float a[FTM];
                uint64_t bb2[FTN / 2];
                *(float4*)&a[0] = *(const float4*)&As[kk * BM + tm0];
                *(float4*)&a[4] = *(const float4*)&As[kk * BM + tm0 + 4];
                *(ulonglong2*)&bb2[0] = *(const ulonglong2*)&Bs[kk * BN + tn0];
                *(ulonglong2*)&bb2[2] = *(const ulonglong2*)&Bs[kk * BN + tn0 + 4];
#pragma unroll
                for (int i = 0; i < FTM; ++i) {
                    const uint64_t aa = pack2(a[i]);
#pragma unroll
                    for (int j = 0; j < FTN / 2; ++j)
                        fma2(acc2[i][j], aa, bb2[j]);
                }
            }
        }

#pragma unroll
        for (int i = 0; i < FTM; ++i) {
            const int t = t0 + tm0 + i;
            float v[FTN];
#pragma unroll
            for (int j = 0; j < FTN / 2; ++j)
                unpack2(acc2[i][j], v[2 * j], v[2 * j + 1]);
            float* o = g_proj + ((size_t)t * B + b) * H + h0 + tn0;
            *(float4*)(o)     = make_float4(v[0], v[1], v[2], v[3]);
            *(float4*)(o + 4) = make_float4(v[4], v[5], v[6], v[7]);
        }
    } else {
        // -------- fp16 2-product MMA (A-dedup), h0 in [256,1024) --------
        const int q  = (bid >> 3) * 6 + (sub - 2);      // 0..1535
        const int hb = q % 6;
        const int r  = q / 6;
        const int tb = r & 3;
        const int b  = r >> 2;
        const int t0 = tb * BM;
        const int h0 = 256 + hb * BN;
        b_done = b;

        const uint32_t sb = s2u(smem);
        const int warp = tid >> 5;
        const int lane = tid & 31;
        const int wm = warp & 1;
        const int wn = warp >> 1;

        const int r0 = tid >> 1;
        const int c0 = (tid * 2) & 3;
        const int c1 = c0 + 1;

        const __half* Abase = g_Ax + ((size_t)(b * T + t0)) * I;
        const __half* Bhb = g_Wh + ((size_t)h0) * I;
        const __half* Blb = g_Wl + ((size_t)h0) * I;

        auto load_stage = [&](int kc) {
            const size_t i0 = (size_t)kc * KC;
            const uint32_t sA  = sb + (kc % STAGES) * STAGE_BYTES;
            const uint32_t sBh = sA + TILE_BYTES;
            const uint32_t sBl = sBh + TILE_BYTES;
            const __half* Ap  = Abase + i0;
            const __half* Bhp = Bhb + i0;
            const __half* Blp = Blb + i0;
            cp16(sA  + r0 * ROWB + c0 * 16, Ap  + (size_t)r0 * I + c0 * 8);
            cp16(sA  + r0 * ROWB + c1 * 16, Ap  + (size_t)r0 * I + c1 * 8);
            cp16(sBh + r0 * ROWB + c0 * 16, Bhp + (size_t)r0 * I + c0 * 8);
            cp16(sBh + r0 * ROWB + c1 * 16, Bhp + (size_t)r0 * I + c1 * 8);
            cp16(sBl + r0 * ROWB + c0 * 16, Blp + (size_t)r0 * I + c0 * 8);
            cp16(sBl + r0 * ROWB + c1 * 16, Blp + (size_t)r0 * I + c1 * 8);
        };

        load_stage(0); cp_commit();
        load_stage(1); cp_commit();

        float acc[4][4][4];
#pragma unroll
        for (int mt = 0; mt < 4; ++mt)
#pragma unroll
            for (int nj = 0; nj < 4; ++nj)
#pragma unroll
                for (int rr = 0; rr < 4; ++rr) acc[mt][nj][rr] = 0.0f;

        const int a_row = (lane & 15);
        const int a_kh  = (lane >> 4) * 8;
        const int b_row = (lane & 7) + ((lane >> 4) << 3);
        const int b_kh  = ((lane >> 3) & 1) * 8;

        for (int s = 0; s < NSTG; ++s) {
            cp_wait<STAGES - 2>();
            __syncthreads();
            if (s + STAGES - 1 < NSTG) load_stage(s + STAGES - 1);
            cp_commit();

            const uint32_t sA  = sb + (s % STAGES) * STAGE_BYTES;
            const uint32_t sBh = sA + TILE_BYTES;
            const uint32_t sBl = sBh + TILE_BYTES;

#pragma unroll
            for (int kk = 0; kk < KC; kk += 16) {
                uint32_t a[4][4], bb[2][4];
#pragma unroll
                for (int mt = 0; mt < 4; ++mt) {
                    const int m = wm * 64 + mt * 16 + a_row;
                    ldm_x4(a[mt][0], a[mt][1], a[mt][2], a[mt][3],
                           sA + m * ROWB + (kk + a_kh) * 2);
                }
#pragma unroll
                for (int nt = 0; nt < 2; ++nt) {
                    const int n = wn * 32 + nt * 16 + b_row;
                    ldm_x4(bb[nt][0], bb[nt][1], bb[nt][2], bb[nt][3],
                           sBh + n * ROWB + (kk + b_kh) * 2);
                }
#pragma unroll
                for (int mt = 0; mt < 4; ++mt)
#pragma unroll
                    for (int nj = 0; nj < 4; ++nj) {
                        const int nt = nj >> 1;
                        const int hh = (nj & 1) * 2;
                        mma16816(acc[mt][nj], a[mt], bb[nt][hh], bb[nt][hh + 1]);
                    }
#pragma unroll
                for (int nt = 0; nt < 2; ++nt) {
                    const int n = wn * 32 + nt * 16 + b_row;
                    ldm_x4(bb[nt][0], bb[nt][1], bb[nt][2], bb[nt][3],
                           sBl + n * ROWB + (kk + b_kh) * 2);
                }
#pragma unroll
                for (int mt = 0; mt < 4; ++mt)
#pragma unroll
                    for (int nj = 0; nj < 4; ++nj) {
                        const int nt = nj >> 1;
                        const int hh = (nj & 1) * 2;
                        mma16816(acc[mt][nj], a[mt], bb[nt][hh], bb[nt][hh + 1]);
                    }
            }
        }

        // Epilogue: add 0.5*rowsum(x) (exact fp32), store proj
#pragma unroll
        for (int mt = 0; mt < 4; ++mt) {
            const int tg = t0 + wm * 64 + mt * 16 + (lane >> 2);
            const float cc0 = g_csum[(size_t)b * T + tg];
            const float cc1 = g_csum[(size_t)b * T + tg + 8];
#pragma unroll
            for (int nj = 0; nj < 4; ++nj) {
                const int h = h0 + wn * 32 + nj * 8 + (lane & 3) * 2;
                float* o0 = g_proj + ((size_t)tg * B + b) * H + h;
                float* o1 = g_proj + ((size_t)(tg + 8) * B + b) * H + h;
                *(float2*)o0 = make_float2(acc[mt][nj][0] + cc0, acc[mt][nj][1] + cc0);
                *(float2*)o1 = make_float2(acc[mt][nj][2] + cc1, acc[mt][nj][3] + cc1);
            }
        }
    }

    // Tile completion signal: all stores done -> fence -> count.
    __syncthreads();
    if (tid == 0) {
        __threadfence();
        atomicAdd(&g_cnt[b_done], 1);
    }
}

// ---------------------------------------------------------------------------
extern "C" void kernel_launch(void* const* d_in, const int* in_sizes, int n_in,
                              void* d_out, int out_size) {
    const float* x    = (const float*)d_in[0];  // (B, I, T)
    const float* W    = (const float*)d_in[1];  // (I, H)
    const float* bias = (const float*)d_in[2];  // (1, H)
    float* out        = (float*)d_out;          // (B, H)

    cudaFuncSetAttribute(gemm_hybrid, cudaFuncAttributeMaxDynamicSharedMemorySize,
                         SMEM_DYN);

    conv_x<<<dim3(T / 32, I / 64, B), dim3(32, 8)>>>(x);
    reduce_csum<<<(B * T) / 256, 256>>>();
    conv_w<<<dim3(H / 32, I / 32), dim3(32, 8)>>>(W);
    gemm_hybrid<<<2048 + 256, 256, SMEM_DYN>>>(x, W, bias, out);
}